// round 1
// baseline (speedup 1.0000x reference)
#include <cuda_runtime.h>

#define BATCH   1024
#define CIN     5
#define NPOS    512
#define DIM     256
#define C4      128
#define NT      32          // positions per block tile
#define SPAD    36          // smem row stride (floats): 32 data + 4 pad
#define KT      16          // k-tile for weight staging
#define THREADS 256

// ---------------- device scratch (global arrays; no allocation) ----------------
__device__ float g_h[(size_t)BATCH * C4 * NPOS];   // 256 MB masked activations
__device__ float g_w1t[CIN * DIM];
__device__ float g_w2t[DIM * DIM];
__device__ float g_w3t[DIM * DIM];
__device__ float g_w4t[DIM * C4];
__device__ float g_wtab[C4 * NPOS];

// ---------------- prep: transpose weights + pooling weight table ----------------
__global__ void prep_kernel(const float* __restrict__ w1, const float* __restrict__ w2,
                            const float* __restrict__ w3, const float* __restrict__ w4,
                            const float* __restrict__ pw)
{
    int i = blockIdx.x * blockDim.x + threadIdx.x;
    if (i < DIM * DIM) {
        int k = i >> 8, c = i & 255;
        g_w2t[i] = w2[c * DIM + k];
        g_w3t[i] = w3[c * DIM + k];
    }
    if (i < DIM * C4) {                 // w4t[k][c], k<256, c<128
        int k = i >> 7, c = i & 127;
        g_w4t[i] = w4[c * DIM + k];
    }
    if (i < CIN * DIM) {
        int k = i / DIM, c = i % DIM;
        g_w1t[i] = w1[c * CIN + k];
    }
    if (i < C4 * NPOS) {
        int c = i >> 9, n = i & 511;
        float ratio = (float)n / 511.0f;          // replicate reference f32 ops
        float pos   = 20.0f * ratio;
        float fidx  = floorf(pos);
        int   idx   = (int)fidx;
        float frac  = pos - fidx;
        int   idx2  = idx + 1; if (idx2 > 20) idx2 = 20;
        g_wtab[i] = (1.0f - frac) * pw[c * 21 + idx] + frac * pw[c * 21 + idx2];
    }
}

// ---------------- dense layer GEMM accumulate (smem-staged weights) ----------------
// Thread t: lane = t&31 owns output channels c = lane + i*32 (i < CO/32),
//           warp = t>>5 owns positions warp*4 .. warp*4+3.
template<int CO>
__device__ __forceinline__ void dense_acc(const float* __restrict__ WT,
                                          const float* sIn, float* sW,
                                          float (*acc)[4],
                                          int tid, int lane, int warp)
{
    const int CPT = CO / 32;
    #pragma unroll 1
    for (int kt = 0; kt < DIM / KT; kt++) {
        __syncthreads();
        // stage KT x CO weight slab
        const float4* src = (const float4*)(WT + kt * KT * CO);
        float4* dst = (float4*)sW;
        for (int idx = tid; idx < KT * CO / 4; idx += THREADS)
            dst[idx] = __ldg(&src[idx]);
        __syncthreads();
        #pragma unroll
        for (int kk = 0; kk < KT; kk++) {
            float4 h = *(const float4*)&sIn[(kt * KT + kk) * SPAD + warp * 4]; // uniform per warp
            #pragma unroll
            for (int i = 0; i < CPT; i++) {
                float w = sW[kk * CO + lane + i * 32];
                acc[i][0] += w * h.x; acc[i][1] += w * h.y;
                acc[i][2] += w * h.z; acc[i][3] += w * h.w;
            }
        }
    }
}

// ---------------- fused 4-layer MLP over a 32-position tile ----------------
__global__ void __launch_bounds__(THREADS, 2)
mlp_kernel(const float* __restrict__ x, const float* __restrict__ mask,
           const float* __restrict__ b1, const float* __restrict__ b2,
           const float* __restrict__ b3, const float* __restrict__ b4)
{
    extern __shared__ float sm[];
    float* bufA = sm;                       // DIM*SPAD
    float* bufB = bufA + DIM * SPAD;        // DIM*SPAD
    float* sW   = bufB + DIM * SPAD;        // KT*DIM
    float* sX   = sW + KT * DIM;            // CIN*SPAD

    const int tid  = threadIdx.x;
    const int lane = tid & 31;
    const int warp = tid >> 5;              // 0..7 -> position group
    const int b    = blockIdx.y;
    const int n0   = blockIdx.x * NT;

    // stage x tile (5 x 32)
    for (int idx = tid; idx < CIN * NT; idx += THREADS) {
        int k = idx / NT, p = idx % NT;
        sX[k * SPAD + p] = x[(b * CIN + k) * NPOS + n0 + p];
    }
    __syncthreads();

    // ---- layer 1: 5 -> 256, relu -> bufA
    {
        float acc[8][4];
        #pragma unroll
        for (int i = 0; i < 8; i++) {
            float bb = __ldg(&b1[lane + i * 32]);
            #pragma unroll
            for (int j = 0; j < 4; j++) acc[i][j] = bb;
        }
        #pragma unroll
        for (int k = 0; k < CIN; k++) {
            float4 h = *(const float4*)&sX[k * SPAD + warp * 4];
            #pragma unroll
            for (int i = 0; i < 8; i++) {
                float w = __ldg(&g_w1t[k * DIM + lane + i * 32]);
                acc[i][0] += w * h.x; acc[i][1] += w * h.y;
                acc[i][2] += w * h.z; acc[i][3] += w * h.w;
            }
        }
        #pragma unroll
        for (int i = 0; i < 8; i++) {
            int c = lane + i * 32;
            #pragma unroll
            for (int j = 0; j < 4; j++)
                bufA[c * SPAD + warp * 4 + j] = fmaxf(acc[i][j], 0.0f);
        }
    }

    // ---- layer 2: 256 -> 256, relu  (bufA -> bufB)
    {
        float acc[8][4];
        #pragma unroll
        for (int i = 0; i < 8; i++) {
            float bb = __ldg(&b2[lane + i * 32]);
            #pragma unroll
            for (int j = 0; j < 4; j++) acc[i][j] = bb;
        }
        dense_acc<DIM>(g_w2t, bufA, sW, acc, tid, lane, warp);
        #pragma unroll
        for (int i = 0; i < 8; i++) {
            int c = lane + i * 32;
            #pragma unroll
            for (int j = 0; j < 4; j++)
                bufB[c * SPAD + warp * 4 + j] = fmaxf(acc[i][j], 0.0f);
        }
    }

    // ---- layer 3: 256 -> 256, relu  (bufB -> bufA)
    {
        float acc[8][4];
        #pragma unroll
        for (int i = 0; i < 8; i++) {
            float bb = __ldg(&b3[lane + i * 32]);
            #pragma unroll
            for (int j = 0; j < 4; j++) acc[i][j] = bb;
        }
        dense_acc<DIM>(g_w3t, bufB, sW, acc, tid, lane, warp);
        #pragma unroll
        for (int i = 0; i < 8; i++) {
            int c = lane + i * 32;
            #pragma unroll
            for (int j = 0; j < 4; j++)
                bufA[c * SPAD + warp * 4 + j] = fmaxf(acc[i][j], 0.0f);
        }
    }

    // ---- layer 4: 256 -> 128, /512, *mask -> g_h[b][c][n]
    {
        float acc[4][4];
        #pragma unroll
        for (int i = 0; i < 4; i++) {
            float bb = __ldg(&b4[lane + i * 32]);
            #pragma unroll
            for (int j = 0; j < 4; j++) acc[i][j] = bb;
        }
        dense_acc<C4>(g_w4t, bufA, sW, acc, tid, lane, warp);
        float mk[4];
        #pragma unroll
        for (int j = 0; j < 4; j++)
            mk[j] = mask[b * NPOS + n0 + warp * 4 + j] * (1.0f / NPOS);
        #pragma unroll
        for (int i = 0; i < 4; i++) {
            int c = lane + i * 32;
            float* dst = g_h + ((size_t)(b * C4 + c) << 9) + n0 + warp * 4;
            #pragma unroll
            for (int j = 0; j < 4; j++)
                dst[j] = acc[i][j] * mk[j];
        }
    }
}

// ---------------- warp-register bitonic sort (desc, 512) + weighted pool ----------------
__global__ void __launch_bounds__(128)
sortpool_kernel(const float* __restrict__ mask, float* __restrict__ out)
{
    const int b    = blockIdx.x;
    const int tid  = threadIdx.x;
    const int lane = tid & 31;
    const int warp = tid >> 5;
    __shared__ float sred[128];

    // size feature: mean(mask)*4
    {
        float s = 0.0f;
        #pragma unroll
        for (int j = 0; j < 4; j++) s += mask[b * NPOS + tid + j * 128];
        sred[tid] = s;
        __syncthreads();
        if (tid == 0) {
            float t = 0.0f;
            for (int i = 0; i < 128; i++) t += sred[i];
            out[b * 129 + 128] = t * (4.0f / NPOS);
        }
    }

    for (int c = warp; c < C4; c += 4) {
        const float* row = g_h + ((size_t)(b * C4 + c) << 9);
        float v[16];
        #pragma unroll
        for (int r = 0; r < 16; r++) v[r] = row[r * 32 + lane];   // elem index = r*32 + lane

        // bitonic sort, descending (all directions flipped)
        #pragma unroll 1
        for (int k = 2; k <= 512; k <<= 1) {
            #pragma unroll 1
            for (int j = k >> 1; j > 0; j >>= 1) {
                if (j >= 32) {
                    int rj = j >> 5;
                    int km = k >> 5;           // k >= 64 here
                    #pragma unroll
                    for (int r = 0; r < 16; r++) {
                        if ((r & rj) == 0) {
                            int r2 = r | rj;
                            bool asc = (r & km) != 0;
                            float a = v[r], bb = v[r2];
                            float lo = fminf(a, bb), hi = fmaxf(a, bb);
                            v[r]  = asc ? lo : hi;
                            v[r2] = asc ? hi : lo;
                        }
                    }
                } else {
                    #pragma unroll
                    for (int r = 0; r < 16; r++) {
                        int i = (r << 5) | lane;
                        bool asc     = (i & k) != 0;
                        bool lower   = (lane & j) == 0;
                        float other  = __shfl_xor_sync(0xffffffffu, v[r], j);
                        bool takeMin = (lower == asc);
                        v[r] = takeMin ? fminf(v[r], other) : fmaxf(v[r], other);
                    }
                }
            }
        }

        // pooled[b][c] = sum sorted * w
        const float* wrow = g_wtab + c * NPOS;
        float s = 0.0f;
        #pragma unroll
        for (int r = 0; r < 16; r++) s += v[r] * wrow[r * 32 + lane];
        #pragma unroll
        for (int o = 16; o > 0; o >>= 1) s += __shfl_xor_sync(0xffffffffu, s, o);
        if (lane == 0) out[b * 129 + c] = s;
    }
}

// ---------------- launch ----------------
extern "C" void kernel_launch(void* const* d_in, const int* in_sizes, int n_in,
                              void* d_out, int out_size)
{
    (void)in_sizes; (void)n_in; (void)out_size;
    const float* x    = (const float*)d_in[0];
    const float* mask = (const float*)d_in[1];
    const float* w1   = (const float*)d_in[2];
    const float* b1   = (const float*)d_in[3];
    const float* w2   = (const float*)d_in[4];
    const float* b2   = (const float*)d_in[5];
    const float* w3   = (const float*)d_in[6];
    const float* b3   = (const float*)d_in[7];
    const float* w4   = (const float*)d_in[8];
    const float* b4   = (const float*)d_in[9];
    const float* pw   = (const float*)d_in[10];
    float* out = (float*)d_out;

    prep_kernel<<<256, 256>>>(w1, w2, w3, w4, pw);

    const int smem = (2 * DIM * SPAD + KT * DIM + CIN * SPAD) * (int)sizeof(float); // ~90.8 KB
    cudaFuncSetAttribute(mlp_kernel, cudaFuncAttributeMaxDynamicSharedMemorySize, smem);
    dim3 grid(NPOS / NT, BATCH);
    mlp_kernel<<<grid, THREADS, smem>>>(x, mask, b1, b2, b3, b4);

    sortpool_kernel<<<BATCH, 128>>>(mask, out);
}

// round 4
// speedup vs baseline: 1.6320x; 1.6320x over previous
#include <cuda_runtime.h>
#include <cuda_bf16.h>
#include <cstdint>

#define BATCH 1024
#define CIN   5
#define NPOS  512
#define DIM   256
#define C4    128
#define MT    64             // positions per CTA
#define AST   264            // act smem row stride (bf16 elems): 528B -> conflict-free
#define WST   72             // weight smem row stride (bf16 elems): 144B -> conflict-free

// smem byte offsets
#define SM_XS   0                       // 5*64 f32 = 1280
#define SM_MK   1280                    // 64 f32 = 256
#define SM_BIAS 1536                    // 896 f32 = 3584
#define SM_ACT  5120                    // 4 act buffers, 64*264*2 = 33792 each
#define SM_AHI  (SM_ACT)
#define SM_ALO  (SM_ACT + 33792)
#define SM_BHI  (SM_ACT + 67584)
#define SM_BLO  (SM_ACT + 101376)
#define SM_WBUF (SM_ACT + 135168)       // 73728 (weight chunk hi+lo; reused as f32 transpose)
#define SM_TOTAL (SM_WBUF + 73728)      // 214016 bytes

// ---------------- device scratch ----------------
__device__ float g_h[(size_t)BATCH * C4 * NPOS];       // 256 MB masked activations
__device__ float g_wtab[C4 * NPOS];
// prepacked weights: per 64-K chunk: [hi: C x 72][lo: C x 72] bf16, chunk-contiguous
__device__ __nv_bfloat16 g_W2p[4 * 2 * 256 * WST];
__device__ __nv_bfloat16 g_W3p[4 * 2 * 256 * WST];
__device__ __nv_bfloat16 g_W4p[4 * 2 * 128 * WST];

// ---------------- helpers ----------------
__device__ __forceinline__ void mma16816(float* d, const unsigned* a, const unsigned* b) {
    asm volatile(
        "mma.sync.aligned.m16n8k16.row.col.f32.bf16.bf16.f32 "
        "{%0,%1,%2,%3}, {%4,%5,%6,%7}, {%8,%9}, {%0,%1,%2,%3};"
        : "+f"(d[0]), "+f"(d[1]), "+f"(d[2]), "+f"(d[3])
        : "r"(a[0]), "r"(a[1]), "r"(a[2]), "r"(a[3]), "r"(b[0]), "r"(b[1]));
}

__device__ __forceinline__ void split2(float a, float b, unsigned& hi, unsigned& lo) {
    __nv_bfloat16 ha = __float2bfloat16_rn(a);
    __nv_bfloat16 hb = __float2bfloat16_rn(b);
    __nv_bfloat162 hp; hp.x = ha; hp.y = hb;
    hi = *(unsigned*)&hp;
    __nv_bfloat162 lp;
    lp.x = __float2bfloat16_rn(a - __bfloat162float(ha));
    lp.y = __float2bfloat16_rn(b - __bfloat162float(hb));
    lo = *(unsigned*)&lp;
}

// ---------------- prep: split+pack weights, pool table ----------------
__global__ void prep_kernel(const float* __restrict__ w2, const float* __restrict__ w3,
                            const float* __restrict__ w4, const float* __restrict__ pw)
{
    int i = blockIdx.x * blockDim.x + threadIdx.x;   // 65536 threads
    int kk = i & 63, c = (i >> 6) & 255, kc = i >> 14;
    int k = kc * 64 + kk;

    float v2 = w2[c * DIM + k];
    __nv_bfloat16 h2 = __float2bfloat16_rn(v2);
    g_W2p[((kc * 2 + 0) * 256 + c) * WST + kk] = h2;
    g_W2p[((kc * 2 + 1) * 256 + c) * WST + kk] = __float2bfloat16_rn(v2 - __bfloat162float(h2));

    float v3 = w3[c * DIM + k];
    __nv_bfloat16 h3 = __float2bfloat16_rn(v3);
    g_W3p[((kc * 2 + 0) * 256 + c) * WST + kk] = h3;
    g_W3p[((kc * 2 + 1) * 256 + c) * WST + kk] = __float2bfloat16_rn(v3 - __bfloat162float(h3));

    if (c < C4) {
        float v4 = w4[c * DIM + k];
        __nv_bfloat16 h4 = __float2bfloat16_rn(v4);
        g_W4p[((kc * 2 + 0) * 128 + c) * WST + kk] = h4;
        g_W4p[((kc * 2 + 1) * 128 + c) * WST + kk] = __float2bfloat16_rn(v4 - __bfloat162float(h4));
    }

    // pool weight table (128 x 512)
    int ch = i >> 9, n = i & 511;
    float ratio = (float)n / 511.0f;
    float pos = 20.0f * ratio;
    float fidx = floorf(pos);
    int idx = (int)fidx;
    float frac = pos - fidx;
    int idx2 = idx + 1; if (idx2 > 20) idx2 = 20;
    g_wtab[i] = (1.0f - frac) * pw[ch * 21 + idx] + frac * pw[ch * 21 + idx2];
}

// ---------------- generic mma layer: COUT outputs, NT n8-tiles per warp ----------------
template<int COUT, int NT>
__device__ __forceinline__ void layer_mma(
    char* smem, const __nv_bfloat16* __restrict__ wglob,
    const __nv_bfloat16* aHi, const __nv_bfloat16* aLo,
    float (*acc)[4], int tid, int wm, int wn, int g, int t2)
{
    __nv_bfloat16* wbuf = (__nv_bfloat16*)(smem + SM_WBUF);
    const int CHUNK_ELEMS = COUT * 2 * WST;     // hi+lo
    #pragma unroll 1
    for (int kc = 0; kc < 4; kc++) {
        __syncthreads();
        const float4* src = (const float4*)(wglob + (size_t)kc * CHUNK_ELEMS);
        float4* dst = (float4*)wbuf;
        const int NF4 = CHUNK_ELEMS / 8;
        for (int i = tid; i < NF4; i += 256) dst[i] = src[i];
        __syncthreads();
        const __nv_bfloat16* wHi = wbuf;
        const __nv_bfloat16* wLo = wbuf + COUT * WST;
        #pragma unroll 1
        for (int ks = 0; ks < 4; ks++) {
            const int kcol = ks * 16 + t2;
            const int row = wm * 16 + g;
            unsigned ahi[4], alo[4];
            ahi[0] = *(const unsigned*)&aHi[(row    ) * AST + kc * 64 + kcol    ];
            ahi[1] = *(const unsigned*)&aHi[(row + 8) * AST + kc * 64 + kcol    ];
            ahi[2] = *(const unsigned*)&aHi[(row    ) * AST + kc * 64 + kcol + 8];
            ahi[3] = *(const unsigned*)&aHi[(row + 8) * AST + kc * 64 + kcol + 8];
            alo[0] = *(const unsigned*)&aLo[(row    ) * AST + kc * 64 + kcol    ];
            alo[1] = *(const unsigned*)&aLo[(row + 8) * AST + kc * 64 + kcol    ];
            alo[2] = *(const unsigned*)&aLo[(row    ) * AST + kc * 64 + kcol + 8];
            alo[3] = *(const unsigned*)&aLo[(row + 8) * AST + kc * 64 + kcol + 8];
            #pragma unroll
            for (int n8 = 0; n8 < NT; n8++) {
                const int c = wn * (NT * 8) + n8 * 8 + g;
                const __nv_bfloat16* ph = wHi + c * WST + kcol;
                const __nv_bfloat16* pl = wLo + c * WST + kcol;
                unsigned bh[2], bl[2];
                bh[0] = *(const unsigned*)ph;       bh[1] = *(const unsigned*)(ph + 8);
                bl[0] = *(const unsigned*)pl;       bl[1] = *(const unsigned*)(pl + 8);
                mma16816(acc[n8], ahi, bh);
                mma16816(acc[n8], ahi, bl);
                mma16816(acc[n8], alo, bh);
            }
        }
    }
}

// ---------------- fused 4-layer MLP, 64 positions per CTA ----------------
__global__ void __launch_bounds__(256, 1)
mlp_kernel(const float* __restrict__ x, const float* __restrict__ mask,
           const float* __restrict__ w1,
           const float* __restrict__ b1, const float* __restrict__ b2,
           const float* __restrict__ b3, const float* __restrict__ b4)
{
    extern __shared__ char smem[];
    const int tid  = threadIdx.x;
    const int lane = tid & 31;
    const int warp = tid >> 5;
    const int wm   = warp & 3;       // m-tile (16 rows each)
    const int wn   = warp >> 2;      // n-half
    const int g    = lane >> 2;
    const int t2   = (lane & 3) * 2;
    const int b    = blockIdx.y;
    const int n0   = blockIdx.x * MT;

    float* xs    = (float*)(smem + SM_XS);
    float* mkS   = (float*)(smem + SM_MK);
    float* sBias = (float*)(smem + SM_BIAS);
    __nv_bfloat16* aAhi = (__nv_bfloat16*)(smem + SM_AHI);
    __nv_bfloat16* aAlo = (__nv_bfloat16*)(smem + SM_ALO);
    __nv_bfloat16* aBhi = (__nv_bfloat16*)(smem + SM_BHI);
    __nv_bfloat16* aBlo = (__nv_bfloat16*)(smem + SM_BLO);

    // stage x tile, mask, biases
    for (int i = tid; i < CIN * MT; i += 256) {
        int k = i / MT, n = i % MT;
        xs[k * MT + n] = x[((size_t)b * CIN + k) * NPOS + n0 + n];
    }
    if (tid < MT) mkS[tid] = mask[(size_t)b * NPOS + n0 + tid] * (1.0f / NPOS);
    for (int i = tid; i < 896; i += 256) {
        float v;
        if      (i < 256) v = b1[i];
        else if (i < 512) v = b2[i - 256];
        else if (i < 768) v = b3[i - 512];
        else              v = b4[i - 768];
        sBias[i] = v;
    }
    __syncthreads();

    // ---- layer 1 (scalar, K=5): thread -> 2 channels x 32 positions
    {
        const int tp  = tid & 127;
        const int ch0 = tp * 2;
        const int nh  = tid >> 7;
        float wr0[CIN], wr1[CIN];
        #pragma unroll
        for (int k = 0; k < CIN; k++) {
            wr0[k] = __ldg(&w1[ch0 * CIN + k]);
            wr1[k] = __ldg(&w1[(ch0 + 1) * CIN + k]);
        }
        const float bb0 = sBias[ch0], bb1 = sBias[ch0 + 1];
        #pragma unroll 4
        for (int nl = 0; nl < 32; nl++) {
            const int n = nh * 32 + nl;
            float a0 = bb0, a1 = bb1;
            #pragma unroll
            for (int k = 0; k < CIN; k++) {
                float xv = xs[k * MT + n];
                a0 += xv * wr0[k];
                a1 += xv * wr1[k];
            }
            a0 = fmaxf(a0, 0.0f); a1 = fmaxf(a1, 0.0f);
            unsigned hi, lo;
            split2(a0, a1, hi, lo);
            *(unsigned*)&aAhi[n * AST + ch0] = hi;
            *(unsigned*)&aAlo[n * AST + ch0] = lo;
        }
    }
    __syncthreads();

    float acc[16][4];

    // ---- layer 2: A -> B
    #pragma unroll
    for (int i = 0; i < 16; i++) { acc[i][0]=acc[i][1]=acc[i][2]=acc[i][3]=0.0f; }
    layer_mma<256, 16>(smem, g_W2p, aAhi, aAlo, acc, tid, wm, wn, g, t2);
    #pragma unroll
    for (int n8 = 0; n8 < 16; n8++) {
        const int col = wn * 128 + n8 * 8 + t2;
        const float bb0 = sBias[256 + col], bb1 = sBias[256 + col + 1];
        #pragma unroll
        for (int half = 0; half < 2; half++) {
            const int row = wm * 16 + g + half * 8;
            float v0 = fmaxf(acc[n8][half * 2 + 0] + bb0, 0.0f);
            float v1 = fmaxf(acc[n8][half * 2 + 1] + bb1, 0.0f);
            unsigned hi, lo;
            split2(v0, v1, hi, lo);
            *(unsigned*)&aBhi[row * AST + col] = hi;
            *(unsigned*)&aBlo[row * AST + col] = lo;
        }
    }
    __syncthreads();

    // ---- layer 3: B -> A
    #pragma unroll
    for (int i = 0; i < 16; i++) { acc[i][0]=acc[i][1]=acc[i][2]=acc[i][3]=0.0f; }
    layer_mma<256, 16>(smem, g_W3p, aBhi, aBlo, acc, tid, wm, wn, g, t2);
    #pragma unroll
    for (int n8 = 0; n8 < 16; n8++) {
        const int col = wn * 128 + n8 * 8 + t2;
        const float bb0 = sBias[512 + col], bb1 = sBias[512 + col + 1];
        #pragma unroll
        for (int half = 0; half < 2; half++) {
            const int row = wm * 16 + g + half * 8;
            float v0 = fmaxf(acc[n8][half * 2 + 0] + bb0, 0.0f);
            float v1 = fmaxf(acc[n8][half * 2 + 1] + bb1, 0.0f);
            unsigned hi, lo;
            split2(v0, v1, hi, lo);
            *(unsigned*)&aAhi[row * AST + col] = hi;
            *(unsigned*)&aAlo[row * AST + col] = lo;
        }
    }
    __syncthreads();

    // ---- layer 4: A -> transpose buffer (f32) -> g_h
    #pragma unroll
    for (int i = 0; i < 8; i++) { acc[i][0]=acc[i][1]=acc[i][2]=acc[i][3]=0.0f; }
    layer_mma<128, 8>(smem, g_W4p, aAhi, aAlo, acc, tid, wm, wn, g, t2);

    float* sT = (float*)(smem + SM_WBUF);   // [128 c][68 n] f32 (reuses weight area)
    __syncthreads();                        // compute done before overwriting wbuf
    #pragma unroll
    for (int n8 = 0; n8 < 8; n8++) {
        const int c = wn * 64 + n8 * 8 + t2;
        const float bb0 = sBias[768 + c], bb1 = sBias[768 + c + 1];
        #pragma unroll
        for (int half = 0; half < 2; half++) {
            const int n = wm * 16 + g + half * 8;
            sT[(c    ) * 68 + n] = acc[n8][half * 2 + 0] + bb0;
            sT[(c + 1) * 68 + n] = acc[n8][half * 2 + 1] + bb1;
        }
    }
    __syncthreads();
    {
        const int c   = tid >> 1;
        const int seg = tid & 1;
        float* dst = g_h + (((size_t)b * C4 + c) << 9) + n0 + seg * 32;
        #pragma unroll
        for (int i = 0; i < 8; i++) {
            const int nn = seg * 32 + i * 4;
            float4 v = *(float4*)&sT[c * 68 + nn];
            v.x *= mkS[nn + 0]; v.y *= mkS[nn + 1];
            v.z *= mkS[nn + 2]; v.w *= mkS[nn + 3];
            *(float4*)&dst[i * 4] = v;
        }
    }
}

// ---------------- warp-register bitonic sort (desc, 512) + weighted pool ----------------
__global__ void __launch_bounds__(256)
sortpool_kernel(const float* __restrict__ mask, float* __restrict__ out)
{
    const int b    = blockIdx.x;
    const int tid  = threadIdx.x;
    const int lane = tid & 31;
    const int warp = tid >> 5;
    __shared__ float sred[8];

    // size feature: mean(mask) * 4
    {
        float s = mask[(size_t)b * NPOS + tid] + mask[(size_t)b * NPOS + tid + 256];
        #pragma unroll
        for (int o = 16; o > 0; o >>= 1) s += __shfl_xor_sync(0xffffffffu, s, o);
        if (lane == 0) sred[warp] = s;
        __syncthreads();
        if (tid == 0) {
            float t = 0.0f;
            #pragma unroll
            for (int i = 0; i < 8; i++) t += sred[i];
            out[b * 129 + 128] = t * (4.0f / NPOS);
        }
    }

    for (int c = warp; c < C4; c += 8) {
        const float* row = g_h + (((size_t)b * C4 + c) << 9);
        float v[16];
        #pragma unroll
        for (int r = 0; r < 16; r++) v[r] = row[r * 32 + lane];

        #pragma unroll 1
        for (int k = 2; k <= 512; k <<= 1) {
            #pragma unroll 1
            for (int j = k >> 1; j > 0; j >>= 1) {
                if (j >= 32) {
                    int rj = j >> 5, km = k >> 5;
                    #pragma unroll
                    for (int r = 0; r < 16; r++) {
                        if ((r & rj) == 0) {
                            int r2 = r | rj;
                            bool asc = (r & km) != 0;
                            float a = v[r], bb = v[r2];
                            float lo = fminf(a, bb), hi = fmaxf(a, bb);
                            v[r]  = asc ? lo : hi;
                            v[r2] = asc ? hi : lo;
                        }
                    }
                } else {
                    #pragma unroll
                    for (int r = 0; r < 16; r++) {
                        int i = (r << 5) | lane;
                        bool asc   = (i & k) != 0;
                        bool lower = (lane & j) == 0;
                        float other = __shfl_xor_sync(0xffffffffu, v[r], j);
                        bool takeMin = (lower == asc);
                        v[r] = takeMin ? fminf(v[r], other) : fmaxf(v[r], other);
                    }
                }
            }
        }

        const float* wrow = g_wtab + c * NPOS;
        float s = 0.0f;
        #pragma unroll
        for (int r = 0; r < 16; r++) s += v[r] * wrow[r * 32 + lane];
        #pragma unroll
        for (int o = 16; o > 0; o >>= 1) s += __shfl_xor_sync(0xffffffffu, s, o);
        if (lane == 0) out[b * 129 + c] = s;
    }
}

// ---------------- launch ----------------
extern "C" void kernel_launch(void* const* d_in, const int* in_sizes, int n_in,
                              void* d_out, int out_size)
{
    (void)in_sizes; (void)n_in; (void)out_size;
    const float* x    = (const float*)d_in[0];
    const float* mask = (const float*)d_in[1];
    const float* w1   = (const float*)d_in[2];
    const float* b1   = (const float*)d_in[3];
    const float* w2   = (const float*)d_in[4];
    const float* b2   = (const float*)d_in[5];
    const float* w3   = (const float*)d_in[6];
    const float* b3   = (const float*)d_in[7];
    const float* w4   = (const float*)d_in[8];
    const float* b4   = (const float*)d_in[9];
    const float* pw   = (const float*)d_in[10];
    float* out = (float*)d_out;

    prep_kernel<<<256, 256>>>(w2, w3, w4, pw);

    cudaFuncSetAttribute(mlp_kernel, cudaFuncAttributeMaxDynamicSharedMemorySize, SM_TOTAL);
    dim3 grid(NPOS / MT, BATCH);
    mlp_kernel<<<grid, 256, SM_TOTAL>>>(x, mask, w1, b1, b2, b3, b4);

    sortpool_kernel<<<BATCH, 256>>>(mask, out);
}

// round 5
// speedup vs baseline: 1.8284x; 1.1204x over previous
#include <cuda_runtime.h>
#include <cuda_bf16.h>
#include <cstdint>

#define BATCH 1024
#define CIN   5
#define NPOS  512
#define DIM   256
#define C4    128
#define MT    64             // positions per CTA
#define AST   264            // act smem row stride (bf16): 132 words, 132%32=4 -> conflict-free
#define WST   40             // weight smem row stride (bf16): 20 words -> conflict-free

// smem byte offsets
#define SM_XS    0                       // 5*64 f32
#define SM_MK    1280                    // 64 f32
#define SM_BIAS  1536                    // 896 f32
#define SM_ACT   5120                    // 4 act buffers, 64*264*2 = 33792 each
#define SM_AHI   (SM_ACT)
#define SM_ALO   (SM_ACT + 33792)
#define SM_BHI   (SM_ACT + 67584)
#define SM_BLO   (SM_ACT + 101376)
#define SM_WBUF  (SM_ACT + 135168)       // double-buffered weight chunks
#define WBUF_SZ  40960
#define SM_TOTAL (SM_WBUF + 2 * WBUF_SZ) // 222208 bytes

// per-chunk byte sizes (32 K-cols, hi+lo)
#define CHB_256  (256 * 2 * WST * 2)     // 40960
#define CHB_128  (128 * 2 * WST * 2)     // 20480

// ---------------- device scratch ----------------
__device__ float g_h[(size_t)BATCH * C4 * NPOS];       // 256 MB masked activations
__device__ float g_wtab[C4 * NPOS];
// prepacked weights: per 32-K chunk: [hi: C x WST][lo: C x WST] bf16, chunk-contiguous
__device__ __align__(16) __nv_bfloat16 g_W2p[8 * 2 * 256 * WST];
__device__ __align__(16) __nv_bfloat16 g_W3p[8 * 2 * 256 * WST];
__device__ __align__(16) __nv_bfloat16 g_W4p[8 * 2 * 128 * WST];

// ---------------- helpers ----------------
__device__ __forceinline__ uint32_t smem_u32(const void* p) {
    uint32_t a;
    asm("{ .reg .u64 t; cvta.to.shared.u64 t, %1; cvt.u32.u64 %0, t; }" : "=r"(a) : "l"(p));
    return a;
}

__device__ __forceinline__ void mma16816(float* d, const unsigned* a, const unsigned* b) {
    asm volatile(
        "mma.sync.aligned.m16n8k16.row.col.f32.bf16.bf16.f32 "
        "{%0,%1,%2,%3}, {%4,%5,%6,%7}, {%8,%9}, {%0,%1,%2,%3};"
        : "+f"(d[0]), "+f"(d[1]), "+f"(d[2]), "+f"(d[3])
        : "r"(a[0]), "r"(a[1]), "r"(a[2]), "r"(a[3]), "r"(b[0]), "r"(b[1]));
}

__device__ __forceinline__ void split2(float a, float b, unsigned& hi, unsigned& lo) {
    __nv_bfloat16 ha = __float2bfloat16_rn(a);
    __nv_bfloat16 hb = __float2bfloat16_rn(b);
    __nv_bfloat162 hp; hp.x = ha; hp.y = hb;
    hi = *(unsigned*)&hp;
    __nv_bfloat162 lp;
    lp.x = __float2bfloat16_rn(a - __bfloat162float(ha));
    lp.y = __float2bfloat16_rn(b - __bfloat162float(hb));
    lo = *(unsigned*)&lp;
}

// all 256 threads: async-copy one weight chunk into ring buffer `buf`
__device__ __forceinline__ void prefetch_chunk(char* smem, int buf, const char* src,
                                               int bytes, int tid)
{
    uint32_t dst = smem_u32(smem + SM_WBUF + buf * WBUF_SZ);
    #pragma unroll 4
    for (int off = tid * 16; off < bytes; off += 256 * 16)
        asm volatile("cp.async.cg.shared.global [%0], [%1], 16;"
                     :: "r"(dst + off), "l"(src + off));
    asm volatile("cp.async.commit_group;" ::: "memory");
}

// ---------------- prep: split+pack weights (chunked), pool table ----------------
__global__ void prep_kernel(const float* __restrict__ w2, const float* __restrict__ w3,
                            const float* __restrict__ w4, const float* __restrict__ pw)
{
    int i = blockIdx.x * blockDim.x + threadIdx.x;   // 65536 threads
    int kk = i & 31, c = (i >> 5) & 255, kc = i >> 13;
    int k = kc * 32 + kk;

    float v2 = w2[c * DIM + k];
    __nv_bfloat16 h2 = __float2bfloat16_rn(v2);
    g_W2p[((kc * 2 + 0) * 256 + c) * WST + kk] = h2;
    g_W2p[((kc * 2 + 1) * 256 + c) * WST + kk] = __float2bfloat16_rn(v2 - __bfloat162float(h2));

    float v3 = w3[c * DIM + k];
    __nv_bfloat16 h3 = __float2bfloat16_rn(v3);
    g_W3p[((kc * 2 + 0) * 256 + c) * WST + kk] = h3;
    g_W3p[((kc * 2 + 1) * 256 + c) * WST + kk] = __float2bfloat16_rn(v3 - __bfloat162float(h3));

    if (c < C4) {
        float v4 = w4[c * DIM + k];
        __nv_bfloat16 h4 = __float2bfloat16_rn(v4);
        g_W4p[((kc * 2 + 0) * 128 + c) * WST + kk] = h4;
        g_W4p[((kc * 2 + 1) * 128 + c) * WST + kk] = __float2bfloat16_rn(v4 - __bfloat162float(h4));
    }

    // pool weight table (128 x 512)
    int ch = i >> 9, n = i & 511;
    float ratio = (float)n / 511.0f;
    float pos = 20.0f * ratio;
    float fidx = floorf(pos);
    int idx = (int)fidx;
    float frac = pos - fidx;
    int idx2 = idx + 1; if (idx2 > 20) idx2 = 20;
    g_wtab[i] = (1.0f - frac) * pw[ch * 21 + idx] + frac * pw[ch * 21 + idx2];
}

// ---------------- mma layer over 8 double-buffered 32-K chunks ----------------
template<int COUT, int NT>
__device__ __forceinline__ void layer_mma(
    char* smem, const __nv_bfloat16* __restrict__ wglob,
    const char* __restrict__ wnext, int next_bytes,
    const __nv_bfloat16* aHi, const __nv_bfloat16* aLo,
    float (*acc)[4], int tid, int wm, int wn, int g, int t2)
{
    const int CHB = COUT * 2 * WST * 2;
    #pragma unroll 1
    for (int kc = 0; kc < 8; kc++) {
        asm volatile("cp.async.wait_group 0;" ::: "memory");
        __syncthreads();
        if (kc < 7)
            prefetch_chunk(smem, (kc + 1) & 1, (const char*)wglob + (size_t)(kc + 1) * CHB, CHB, tid);
        else if (wnext)
            prefetch_chunk(smem, 0, wnext, next_bytes, tid);

        const __nv_bfloat16* wHi = (const __nv_bfloat16*)(smem + SM_WBUF + (kc & 1) * WBUF_SZ);
        const __nv_bfloat16* wLo = wHi + COUT * WST;

        #pragma unroll
        for (int ks = 0; ks < 2; ks++) {
            const int kcol = ks * 16 + t2;
            const int row = wm * 16 + g;
            const int acol = kc * 32 + kcol;
            unsigned ahi[4], alo[4];
            ahi[0] = *(const unsigned*)&aHi[(row    ) * AST + acol    ];
            ahi[1] = *(const unsigned*)&aHi[(row + 8) * AST + acol    ];
            ahi[2] = *(const unsigned*)&aHi[(row    ) * AST + acol + 8];
            ahi[3] = *(const unsigned*)&aHi[(row + 8) * AST + acol + 8];
            alo[0] = *(const unsigned*)&aLo[(row    ) * AST + acol    ];
            alo[1] = *(const unsigned*)&aLo[(row + 8) * AST + acol    ];
            alo[2] = *(const unsigned*)&aLo[(row    ) * AST + acol + 8];
            alo[3] = *(const unsigned*)&aLo[(row + 8) * AST + acol + 8];
            #pragma unroll
            for (int n8 = 0; n8 < NT; n8++) {
                const int c = wn * (NT * 8) + n8 * 8 + g;
                const __nv_bfloat16* ph = wHi + c * WST + kcol;
                const __nv_bfloat16* pl = wLo + c * WST + kcol;
                unsigned bh[2], bl[2];
                bh[0] = *(const unsigned*)ph;       bh[1] = *(const unsigned*)(ph + 8);
                bl[0] = *(const unsigned*)pl;       bl[1] = *(const unsigned*)(pl + 8);
                mma16816(acc[n8], ahi, bh);
                mma16816(acc[n8], ahi, bl);
                mma16816(acc[n8], alo, bh);
            }
        }
    }
}

// ---------------- fused 4-layer MLP, 64 positions per CTA ----------------
__global__ void __launch_bounds__(256, 1)
mlp_kernel(const float* __restrict__ x, const float* __restrict__ mask,
           const float* __restrict__ w1,
           const float* __restrict__ b1, const float* __restrict__ b2,
           const float* __restrict__ b3, const float* __restrict__ b4)
{
    extern __shared__ char smem[];
    const int tid  = threadIdx.x;
    const int lane = tid & 31;
    const int warp = tid >> 5;
    const int wm   = warp & 3;       // m-tile (16 rows)
    const int wn   = warp >> 2;      // n-half
    const int g    = lane >> 2;
    const int t2   = (lane & 3) * 2;
    const int b    = blockIdx.y;
    const int n0   = blockIdx.x * MT;

    // kick off layer-2 chunk 0 immediately (covered by layer-1 scalar work)
    prefetch_chunk(smem, 0, (const char*)g_W2p, CHB_256, tid);

    float* xs    = (float*)(smem + SM_XS);
    float* mkS   = (float*)(smem + SM_MK);
    float* sBias = (float*)(smem + SM_BIAS);
    __nv_bfloat16* aAhi = (__nv_bfloat16*)(smem + SM_AHI);
    __nv_bfloat16* aAlo = (__nv_bfloat16*)(smem + SM_ALO);
    __nv_bfloat16* aBhi = (__nv_bfloat16*)(smem + SM_BHI);
    __nv_bfloat16* aBlo = (__nv_bfloat16*)(smem + SM_BLO);

    // stage x tile, mask, biases
    for (int i = tid; i < CIN * MT; i += 256) {
        int k = i / MT, n = i % MT;
        xs[k * MT + n] = x[((size_t)b * CIN + k) * NPOS + n0 + n];
    }
    if (tid < MT) mkS[tid] = mask[(size_t)b * NPOS + n0 + tid] * (1.0f / NPOS);
    for (int i = tid; i < 896; i += 256) {
        float v;
        if      (i < 256) v = b1[i];
        else if (i < 512) v = b2[i - 256];
        else if (i < 768) v = b3[i - 512];
        else              v = b4[i - 768];
        sBias[i] = v;
    }
    __syncthreads();

    // ---- layer 1 (scalar, K=5): thread -> 2 channels x 32 positions
    {
        const int tp  = tid & 127;
        const int ch0 = tp * 2;
        const int nh  = tid >> 7;
        float wr0[CIN], wr1[CIN];
        #pragma unroll
        for (int k = 0; k < CIN; k++) {
            wr0[k] = __ldg(&w1[ch0 * CIN + k]);
            wr1[k] = __ldg(&w1[(ch0 + 1) * CIN + k]);
        }
        const float bb0 = sBias[ch0], bb1 = sBias[ch0 + 1];
        #pragma unroll 4
        for (int nl = 0; nl < 32; nl++) {
            const int n = nh * 32 + nl;
            float a0 = bb0, a1 = bb1;
            #pragma unroll
            for (int k = 0; k < CIN; k++) {
                float xv = xs[k * MT + n];
                a0 += xv * wr0[k];
                a1 += xv * wr1[k];
            }
            a0 = fmaxf(a0, 0.0f); a1 = fmaxf(a1, 0.0f);
            unsigned hi, lo;
            split2(a0, a1, hi, lo);
            *(unsigned*)&aAhi[n * AST + ch0] = hi;
            *(unsigned*)&aAlo[n * AST + ch0] = lo;
        }
    }
    __syncthreads();

    float acc[16][4];

    // ---- layer 2: A -> B
    #pragma unroll
    for (int i = 0; i < 16; i++) { acc[i][0]=acc[i][1]=acc[i][2]=acc[i][3]=0.0f; }
    layer_mma<256, 16>(smem, g_W2p, (const char*)g_W3p, CHB_256, aAhi, aAlo, acc, tid, wm, wn, g, t2);
    #pragma unroll
    for (int n8 = 0; n8 < 16; n8++) {
        const int col = wn * 128 + n8 * 8 + t2;
        const float bb0 = sBias[256 + col], bb1 = sBias[256 + col + 1];
        #pragma unroll
        for (int half = 0; half < 2; half++) {
            const int row = wm * 16 + g + half * 8;
            float v0 = fmaxf(acc[n8][half * 2 + 0] + bb0, 0.0f);
            float v1 = fmaxf(acc[n8][half * 2 + 1] + bb1, 0.0f);
            unsigned hi, lo;
            split2(v0, v1, hi, lo);
            *(unsigned*)&aBhi[row * AST + col] = hi;
            *(unsigned*)&aBlo[row * AST + col] = lo;
        }
    }
    __syncthreads();

    // ---- layer 3: B -> A
    #pragma unroll
    for (int i = 0; i < 16; i++) { acc[i][0]=acc[i][1]=acc[i][2]=acc[i][3]=0.0f; }
    layer_mma<256, 16>(smem, g_W3p, (const char*)g_W4p, CHB_128, aBhi, aBlo, acc, tid, wm, wn, g, t2);
    #pragma unroll
    for (int n8 = 0; n8 < 16; n8++) {
        const int col = wn * 128 + n8 * 8 + t2;
        const float bb0 = sBias[512 + col], bb1 = sBias[512 + col + 1];
        #pragma unroll
        for (int half = 0; half < 2; half++) {
            const int row = wm * 16 + g + half * 8;
            float v0 = fmaxf(acc[n8][half * 2 + 0] + bb0, 0.0f);
            float v1 = fmaxf(acc[n8][half * 2 + 1] + bb1, 0.0f);
            unsigned hi, lo;
            split2(v0, v1, hi, lo);
            *(unsigned*)&aAhi[row * AST + col] = hi;
            *(unsigned*)&aAlo[row * AST + col] = lo;
        }
    }
    __syncthreads();

    // ---- layer 4: A -> transpose buffer (f32) -> g_h
    #pragma unroll
    for (int i = 0; i < 8; i++) { acc[i][0]=acc[i][1]=acc[i][2]=acc[i][3]=0.0f; }
    layer_mma<128, 8>(smem, g_W4p, (const char*)0, 0, aAhi, aAlo, acc, tid, wm, wn, g, t2);

    float* sT = (float*)(smem + SM_WBUF);   // [128 c][68 n] f32, reuses weight ring
    __syncthreads();                        // all MMA reads of wbuf done
    #pragma unroll
    for (int n8 = 0; n8 < 8; n8++) {
        const int c = wn * 64 + n8 * 8 + t2;
        const float bb0 = sBias[768 + c], bb1 = sBias[768 + c + 1];
        #pragma unroll
        for (int half = 0; half < 2; half++) {
            const int n = wm * 16 + g + half * 8;
            sT[(c    ) * 68 + n] = acc[n8][half * 2 + 0] + bb0;
            sT[(c + 1) * 68 + n] = acc[n8][half * 2 + 1] + bb1;
        }
    }
    __syncthreads();
    {
        const int c   = tid >> 1;
        const int seg = tid & 1;
        float* dst = g_h + (((size_t)b * C4 + c) << 9) + n0 + seg * 32;
        #pragma unroll
        for (int i = 0; i < 8; i++) {
            const int nn = seg * 32 + i * 4;
            float4 v = *(float4*)&sT[c * 68 + nn];
            v.x *= mkS[nn + 0]; v.y *= mkS[nn + 1];
            v.z *= mkS[nn + 2]; v.w *= mkS[nn + 3];
            *(float4*)&dst[i * 4] = v;
        }
    }
}

// ---------------- warp-register bitonic sort (desc, 512) + weighted pool ----------------
__global__ void __launch_bounds__(256)
sortpool_kernel(const float* __restrict__ mask, float* __restrict__ out)
{
    const int b    = blockIdx.x;
    const int tid  = threadIdx.x;
    const int lane = tid & 31;
    const int warp = tid >> 5;
    __shared__ float sred[8];

    // size feature: mean(mask) * 4
    {
        float s = mask[(size_t)b * NPOS + tid] + mask[(size_t)b * NPOS + tid + 256];
        #pragma unroll
        for (int o = 16; o > 0; o >>= 1) s += __shfl_xor_sync(0xffffffffu, s, o);
        if (lane == 0) sred[warp] = s;
        __syncthreads();
        if (tid == 0) {
            float t = 0.0f;
            #pragma unroll
            for (int i = 0; i < 8; i++) t += sred[i];
            out[b * 129 + 128] = t * (4.0f / NPOS);
        }
    }

    for (int c = warp; c < C4; c += 8) {
        const float* row = g_h + (((size_t)b * C4 + c) << 9);
        float v[16];
        #pragma unroll
        for (int r = 0; r < 16; r++) v[r] = row[r * 32 + lane];

        #pragma unroll 1
        for (int k = 2; k <= 512; k <<= 1) {
            #pragma unroll 1
            for (int j = k >> 1; j > 0; j >>= 1) {
                if (j >= 32) {
                    int rj = j >> 5, km = k >> 5;
                    #pragma unroll
                    for (int r = 0; r < 16; r++) {
                        if ((r & rj) == 0) {
                            int r2 = r | rj;
                            bool asc = (r & km) != 0;
                            float a = v[r], bb = v[r2];
                            float lo = fminf(a, bb), hi = fmaxf(a, bb);
                            v[r]  = asc ? lo : hi;
                            v[r2] = asc ? hi : lo;
                        }
                    }
                } else {
                    #pragma unroll
                    for (int r = 0; r < 16; r++) {
                        int i = (r << 5) | lane;
                        bool asc   = (i & k) != 0;
                        bool lower = (lane & j) == 0;
                        float other = __shfl_xor_sync(0xffffffffu, v[r], j);
                        bool takeMin = (lower == asc);
                        v[r] = takeMin ? fminf(v[r], other) : fmaxf(v[r], other);
                    }
                }
            }
        }

        const float* wrow = g_wtab + c * NPOS;
        float s = 0.0f;
        #pragma unroll
        for (int r = 0; r < 16; r++) s += v[r] * wrow[r * 32 + lane];
        #pragma unroll
        for (int o = 16; o > 0; o >>= 1) s += __shfl_xor_sync(0xffffffffu, s, o);
        if (lane == 0) out[b * 129 + c] = s;
    }
}

// ---------------- launch ----------------
extern "C" void kernel_launch(void* const* d_in, const int* in_sizes, int n_in,
                              void* d_out, int out_size)
{
    (void)in_sizes; (void)n_in; (void)out_size;
    const float* x    = (const float*)d_in[0];
    const float* mask = (const float*)d_in[1];
    const float* w1   = (const float*)d_in[2];
    const float* b1   = (const float*)d_in[3];
    const float* w2   = (const float*)d_in[4];
    const float* b2   = (const float*)d_in[5];
    const float* w3   = (const float*)d_in[6];
    const float* b3   = (const float*)d_in[7];
    const float* w4   = (const float*)d_in[8];
    const float* b4   = (const float*)d_in[9];
    const float* pw   = (const float*)d_in[10];
    float* out = (float*)d_out;

    prep_kernel<<<256, 256>>>(w2, w3, w4, pw);

    cudaFuncSetAttribute(mlp_kernel, cudaFuncAttributeMaxDynamicSharedMemorySize, SM_TOTAL);
    dim3 grid(NPOS / MT, BATCH);
    mlp_kernel<<<grid, 256, SM_TOTAL>>>(x, mask, w1, b1, b2, b3, b4);

    sortpool_kernel<<<BATCH, 256>>>(mask, out);
}

// round 6
// speedup vs baseline: 1.9917x; 1.0893x over previous
#include <cuda_runtime.h>
#include <cuda_bf16.h>
#include <cstdint>

#define BATCH 1024
#define CIN   5
#define NPOS  512
#define DIM   256
#define C4    128
#define MT    128            // positions per CTA
#define AST   264            // act smem row stride (bf16): 132 words -> conflict-free
#define WST   40             // weight smem row stride (bf16): 20 words -> conflict-free

// smem byte offsets
#define SM_XS    0                       // 5*128 f32 = 2560
#define SM_MK    2560                    // 128 f32 = 512
#define SM_BIAS  3072                    // 896 f32 = 3584
#define SM_ACT   6656                    // 2 act buffers (in-place across layers)
#define SM_AHI   (SM_ACT)                // 128*264*2 = 67584
#define SM_ALO   (SM_ACT + 67584)
#define SM_WBUF  (SM_ACT + 135168)       // double-buffered weight chunks
#define WBUF_SZ  40960
#define SM_TOTAL (SM_WBUF + 2 * WBUF_SZ) // 223744 bytes

// per-chunk byte sizes (32 K-cols, hi+lo)
#define CHB_256  (256 * 2 * WST * 2)     // 40960
#define CHB_128  (128 * 2 * WST * 2)     // 20480

// ---------------- device scratch ----------------
__device__ float g_h[(size_t)BATCH * C4 * NPOS];       // 256 MB masked activations
__device__ float g_wtab[C4 * NPOS];
// prepacked weights: per 32-K chunk: [hi: C x WST][lo: C x WST] bf16, chunk-contiguous
__device__ __align__(16) __nv_bfloat16 g_W2p[8 * 2 * 256 * WST];
__device__ __align__(16) __nv_bfloat16 g_W3p[8 * 2 * 256 * WST];
__device__ __align__(16) __nv_bfloat16 g_W4p[8 * 2 * 128 * WST];

// ---------------- helpers ----------------
__device__ __forceinline__ uint32_t smem_u32(const void* p) {
    uint32_t a;
    asm("{ .reg .u64 t; cvta.to.shared.u64 t, %1; cvt.u32.u64 %0, t; }" : "=r"(a) : "l"(p));
    return a;
}

__device__ __forceinline__ void mma16816(float* d, const unsigned* a, const unsigned* b) {
    asm volatile(
        "mma.sync.aligned.m16n8k16.row.col.f32.bf16.bf16.f32 "
        "{%0,%1,%2,%3}, {%4,%5,%6,%7}, {%8,%9}, {%0,%1,%2,%3};"
        : "+f"(d[0]), "+f"(d[1]), "+f"(d[2]), "+f"(d[3])
        : "r"(a[0]), "r"(a[1]), "r"(a[2]), "r"(a[3]), "r"(b[0]), "r"(b[1]));
}

__device__ __forceinline__ void split2(float a, float b, unsigned& hi, unsigned& lo) {
    __nv_bfloat16 ha = __float2bfloat16_rn(a);
    __nv_bfloat16 hb = __float2bfloat16_rn(b);
    __nv_bfloat162 hp; hp.x = ha; hp.y = hb;
    hi = *(unsigned*)&hp;
    __nv_bfloat162 lp;
    lp.x = __float2bfloat16_rn(a - __bfloat162float(ha));
    lp.y = __float2bfloat16_rn(b - __bfloat162float(hb));
    lo = *(unsigned*)&lp;
}

// all 256 threads: async-copy one weight chunk into ring buffer `buf`
__device__ __forceinline__ void prefetch_chunk(char* smem, int buf, const char* src,
                                               int bytes, int tid)
{
    uint32_t dst = smem_u32(smem + SM_WBUF + buf * WBUF_SZ);
    #pragma unroll 4
    for (int off = tid * 16; off < bytes; off += 256 * 16)
        asm volatile("cp.async.cg.shared.global [%0], [%1], 16;"
                     :: "r"(dst + off), "l"(src + off));
    asm volatile("cp.async.commit_group;" ::: "memory");
}

// ---------------- prep: split+pack weights (chunked), pool table ----------------
__global__ void prep_kernel(const float* __restrict__ w2, const float* __restrict__ w3,
                            const float* __restrict__ w4, const float* __restrict__ pw)
{
    int i = blockIdx.x * blockDim.x + threadIdx.x;   // 65536 threads
    int kk = i & 31, c = (i >> 5) & 255, kc = i >> 13;
    int k = kc * 32 + kk;

    float v2 = w2[c * DIM + k];
    __nv_bfloat16 h2 = __float2bfloat16_rn(v2);
    g_W2p[((kc * 2 + 0) * 256 + c) * WST + kk] = h2;
    g_W2p[((kc * 2 + 1) * 256 + c) * WST + kk] = __float2bfloat16_rn(v2 - __bfloat162float(h2));

    float v3 = w3[c * DIM + k];
    __nv_bfloat16 h3 = __float2bfloat16_rn(v3);
    g_W3p[((kc * 2 + 0) * 256 + c) * WST + kk] = h3;
    g_W3p[((kc * 2 + 1) * 256 + c) * WST + kk] = __float2bfloat16_rn(v3 - __bfloat162float(h3));

    if (c < C4) {
        float v4 = w4[c * DIM + k];
        __nv_bfloat16 h4 = __float2bfloat16_rn(v4);
        g_W4p[((kc * 2 + 0) * 128 + c) * WST + kk] = h4;
        g_W4p[((kc * 2 + 1) * 128 + c) * WST + kk] = __float2bfloat16_rn(v4 - __bfloat162float(h4));
    }

    // pool weight table (128 x 512)
    int ch = i >> 9, n = i & 511;
    float ratio = (float)n / 511.0f;
    float pos = 20.0f * ratio;
    float fidx = floorf(pos);
    int idx = (int)fidx;
    float frac = pos - fidx;
    int idx2 = idx + 1; if (idx2 > 20) idx2 = 20;
    g_wtab[i] = (1.0f - frac) * pw[ch * 21 + idx] + frac * pw[ch * 21 + idx2];
}

// ---------------- mma layer over 8 double-buffered 32-K chunks, 2 m-tiles/warp ----------------
template<int COUT, int NT>
__device__ __forceinline__ void layer_mma(
    char* smem, const __nv_bfloat16* __restrict__ wglob,
    const char* __restrict__ wnext, int next_bytes,
    const __nv_bfloat16* aHi, const __nv_bfloat16* aLo,
    float (*acc0)[4], float (*acc1)[4],
    int tid, int wm, int wn, int g, int t2)
{
    const int CHB = COUT * 2 * WST * 2;
    #pragma unroll 1
    for (int kc = 0; kc < 8; kc++) {
        asm volatile("cp.async.wait_group 0;" ::: "memory");
        __syncthreads();
        if (kc < 7)
            prefetch_chunk(smem, (kc + 1) & 1, (const char*)wglob + (size_t)(kc + 1) * CHB, CHB, tid);
        else if (wnext)
            prefetch_chunk(smem, 0, wnext, next_bytes, tid);

        const __nv_bfloat16* wHi = (const __nv_bfloat16*)(smem + SM_WBUF + (kc & 1) * WBUF_SZ);
        const __nv_bfloat16* wLo = wHi + COUT * WST;

        #pragma unroll
        for (int ks = 0; ks < 2; ks++) {
            const int kcol = ks * 16 + t2;
            const int acol = kc * 32 + kcol;
            const int row0 = wm * 32 + g;         // m-tile 0
            const int row1 = row0 + 16;           // m-tile 1
            unsigned ahi0[4], alo0[4], ahi1[4], alo1[4];
            ahi0[0] = *(const unsigned*)&aHi[(row0    ) * AST + acol    ];
            ahi0[1] = *(const unsigned*)&aHi[(row0 + 8) * AST + acol    ];
            ahi0[2] = *(const unsigned*)&aHi[(row0    ) * AST + acol + 8];
            ahi0[3] = *(const unsigned*)&aHi[(row0 + 8) * AST + acol + 8];
            alo0[0] = *(const unsigned*)&aLo[(row0    ) * AST + acol    ];
            alo0[1] = *(const unsigned*)&aLo[(row0 + 8) * AST + acol    ];
            alo0[2] = *(const unsigned*)&aLo[(row0    ) * AST + acol + 8];
            alo0[3] = *(const unsigned*)&aLo[(row0 + 8) * AST + acol + 8];
            ahi1[0] = *(const unsigned*)&aHi[(row1    ) * AST + acol    ];
            ahi1[1] = *(const unsigned*)&aHi[(row1 + 8) * AST + acol    ];
            ahi1[2] = *(const unsigned*)&aHi[(row1    ) * AST + acol + 8];
            ahi1[3] = *(const unsigned*)&aHi[(row1 + 8) * AST + acol + 8];
            alo1[0] = *(const unsigned*)&aLo[(row1    ) * AST + acol    ];
            alo1[1] = *(const unsigned*)&aLo[(row1 + 8) * AST + acol    ];
            alo1[2] = *(const unsigned*)&aLo[(row1    ) * AST + acol + 8];
            alo1[3] = *(const unsigned*)&aLo[(row1 + 8) * AST + acol + 8];
            #pragma unroll
            for (int n8 = 0; n8 < NT; n8++) {
                const int c = wn * (NT * 8) + n8 * 8 + g;
                const __nv_bfloat16* ph = wHi + c * WST + kcol;
                const __nv_bfloat16* pl = wLo + c * WST + kcol;
                unsigned bh[2], bl[2];
                bh[0] = *(const unsigned*)ph;       bh[1] = *(const unsigned*)(ph + 8);
                bl[0] = *(const unsigned*)pl;       bl[1] = *(const unsigned*)(pl + 8);
                mma16816(acc0[n8], ahi0, bh);
                mma16816(acc0[n8], ahi0, bl);
                mma16816(acc0[n8], alo0, bh);
                mma16816(acc1[n8], ahi1, bh);
                mma16816(acc1[n8], ahi1, bl);
                mma16816(acc1[n8], alo1, bh);
            }
        }
    }
}

// ---------------- fused 4-layer MLP, 128 positions per CTA ----------------
__global__ void __launch_bounds__(256, 1)
mlp_kernel(const float* __restrict__ x, const float* __restrict__ mask,
           const float* __restrict__ w1,
           const float* __restrict__ b1, const float* __restrict__ b2,
           const float* __restrict__ b3, const float* __restrict__ b4)
{
    extern __shared__ char smem[];
    const int tid  = threadIdx.x;
    const int lane = tid & 31;
    const int warp = tid >> 5;
    const int wm   = warp & 3;       // 32-row group
    const int wn   = warp >> 2;      // n-half
    const int g    = lane >> 2;
    const int t2   = (lane & 3) * 2;
    const int b    = blockIdx.y;
    const int n0   = blockIdx.x * MT;

    // kick off layer-2 chunk 0 immediately (covered by layer-1 scalar work)
    prefetch_chunk(smem, 0, (const char*)g_W2p, CHB_256, tid);

    float* xs    = (float*)(smem + SM_XS);
    float* mkS   = (float*)(smem + SM_MK);
    float* sBias = (float*)(smem + SM_BIAS);
    __nv_bfloat16* aHi = (__nv_bfloat16*)(smem + SM_AHI);
    __nv_bfloat16* aLo = (__nv_bfloat16*)(smem + SM_ALO);

    // stage x tile, mask, biases
    for (int i = tid; i < CIN * MT; i += 256) {
        int k = i / MT, n = i % MT;
        xs[k * MT + n] = x[((size_t)b * CIN + k) * NPOS + n0 + n];
    }
    if (tid < MT) mkS[tid] = mask[(size_t)b * NPOS + n0 + tid] * (1.0f / NPOS);
    for (int i = tid; i < 896; i += 256) {
        float v;
        if      (i < 256) v = b1[i];
        else if (i < 512) v = b2[i - 256];
        else if (i < 768) v = b3[i - 512];
        else              v = b4[i - 768];
        sBias[i] = v;
    }
    __syncthreads();

    // ---- layer 1 (scalar, K=5): thread -> 2 channels x 64 positions
    {
        const int tp  = tid & 127;
        const int ch0 = tp * 2;
        const int nh  = tid >> 7;
        float wr0[CIN], wr1[CIN];
        #pragma unroll
        for (int k = 0; k < CIN; k++) {
            wr0[k] = __ldg(&w1[ch0 * CIN + k]);
            wr1[k] = __ldg(&w1[(ch0 + 1) * CIN + k]);
        }
        const float bb0 = sBias[ch0], bb1 = sBias[ch0 + 1];
        #pragma unroll 4
        for (int nl = 0; nl < 64; nl++) {
            const int n = nh * 64 + nl;
            float a0 = bb0, a1 = bb1;
            #pragma unroll
            for (int k = 0; k < CIN; k++) {
                float xv = xs[k * MT + n];
                a0 += xv * wr0[k];
                a1 += xv * wr1[k];
            }
            a0 = fmaxf(a0, 0.0f); a1 = fmaxf(a1, 0.0f);
            unsigned hi, lo;
            split2(a0, a1, hi, lo);
            *(unsigned*)&aHi[n * AST + ch0] = hi;
            *(unsigned*)&aLo[n * AST + ch0] = lo;
        }
    }
    __syncthreads();

    float acc0[16][4], acc1[16][4];

    // ---- layers 2 and 3 (in-place act update)
    #pragma unroll 1
    for (int L = 0; L < 2; L++) {
        #pragma unroll
        for (int i = 0; i < 16; i++) {
            acc0[i][0]=acc0[i][1]=acc0[i][2]=acc0[i][3]=0.0f;
            acc1[i][0]=acc1[i][1]=acc1[i][2]=acc1[i][3]=0.0f;
        }
        const __nv_bfloat16* wg = (L == 0) ? g_W2p : g_W3p;
        const char* wnxt = (L == 0) ? (const char*)g_W3p : (const char*)g_W4p;
        const int nb = (L == 0) ? CHB_256 : CHB_128;
        layer_mma<256, 16>(smem, wg, wnxt, nb, aHi, aLo, acc0, acc1, tid, wm, wn, g, t2);
        __syncthreads();                 // all MMA reads done before in-place overwrite
        const float* lb = sBias + 256 * (L + 1);
        #pragma unroll
        for (int n8 = 0; n8 < 16; n8++) {
            const int col = wn * 128 + n8 * 8 + t2;
            const float bb0 = lb[col], bb1 = lb[col + 1];
            #pragma unroll
            for (int half = 0; half < 2; half++) {
                const int r0 = wm * 32 + g + half * 8;
                float v0 = fmaxf(acc0[n8][half * 2 + 0] + bb0, 0.0f);
                float v1 = fmaxf(acc0[n8][half * 2 + 1] + bb1, 0.0f);
                unsigned hi, lo;
                split2(v0, v1, hi, lo);
                *(unsigned*)&aHi[r0 * AST + col] = hi;
                *(unsigned*)&aLo[r0 * AST + col] = lo;
                const int r1 = r0 + 16;
                v0 = fmaxf(acc1[n8][half * 2 + 0] + bb0, 0.0f);
                v1 = fmaxf(acc1[n8][half * 2 + 1] + bb1, 0.0f);
                split2(v0, v1, hi, lo);
                *(unsigned*)&aHi[r1 * AST + col] = hi;
                *(unsigned*)&aLo[r1 * AST + col] = lo;
            }
        }
        __syncthreads();
    }

    // ---- layer 4: A -> transpose buffer (f32) -> g_h
    #pragma unroll
    for (int i = 0; i < 8; i++) {
        acc0[i][0]=acc0[i][1]=acc0[i][2]=acc0[i][3]=0.0f;
        acc1[i][0]=acc1[i][1]=acc1[i][2]=acc1[i][3]=0.0f;
    }
    layer_mma<128, 8>(smem, g_W4p, (const char*)0, 0, aHi, aLo, acc0, acc1, tid, wm, wn, g, t2);

    float* sT = (float*)(smem + SM_WBUF);   // [128 c][132 n] f32, reuses weight ring
    __syncthreads();                        // all MMA reads of wbuf done
    #pragma unroll
    for (int n8 = 0; n8 < 8; n8++) {
        const int c = wn * 64 + n8 * 8 + t2;
        const float bb0 = sBias[768 + c], bb1 = sBias[768 + c + 1];
        #pragma unroll
        for (int half = 0; half < 2; half++) {
            const int n0r = wm * 32 + g + half * 8;
            sT[(c    ) * 132 + n0r] = acc0[n8][half * 2 + 0] + bb0;
            sT[(c + 1) * 132 + n0r] = acc0[n8][half * 2 + 1] + bb1;
            sT[(c    ) * 132 + n0r + 16] = acc1[n8][half * 2 + 0] + bb0;
            sT[(c + 1) * 132 + n0r + 16] = acc1[n8][half * 2 + 1] + bb1;
        }
    }
    __syncthreads();
    {
        const int c   = tid >> 1;
        const int seg = tid & 1;
        float* dst = g_h + (((size_t)b * C4 + c) << 9) + n0 + seg * 64;
        #pragma unroll
        for (int i = 0; i < 16; i++) {
            const int nn = seg * 64 + i * 4;
            float4 v = *(float4*)&sT[c * 132 + nn];
            v.x *= mkS[nn + 0]; v.y *= mkS[nn + 1];
            v.z *= mkS[nn + 2]; v.w *= mkS[nn + 3];
            *(float4*)&dst[i * 4] = v;
        }
    }
}

// ---------------- warp-register bitonic sort (desc, 512) + weighted pool ----------------
__global__ void __launch_bounds__(256)
sortpool_kernel(const float* __restrict__ mask, float* __restrict__ out)
{
    const int b    = blockIdx.x;
    const int tid  = threadIdx.x;
    const int lane = tid & 31;
    const int warp = tid >> 5;
    __shared__ float sred[8];

    // size feature: mean(mask) * 4
    {
        float s = mask[(size_t)b * NPOS + tid] + mask[(size_t)b * NPOS + tid + 256];
        #pragma unroll
        for (int o = 16; o > 0; o >>= 1) s += __shfl_xor_sync(0xffffffffu, s, o);
        if (lane == 0) sred[warp] = s;
        __syncthreads();
        if (tid == 0) {
            float t = 0.0f;
            #pragma unroll
            for (int i = 0; i < 8; i++) t += sred[i];
            out[b * 129 + 128] = t * (4.0f / NPOS);
        }
    }

    for (int c = warp; c < C4; c += 8) {
        const float* row = g_h + (((size_t)b * C4 + c) << 9);
        float v[16];
        #pragma unroll
        for (int r = 0; r < 16; r++) v[r] = row[r * 32 + lane];

        #pragma unroll 1
        for (int k = 2; k <= 512; k <<= 1) {
            #pragma unroll 1
            for (int j = k >> 1; j > 0; j >>= 1) {
                if (j >= 32) {
                    int rj = j >> 5, km = k >> 5;
                    #pragma unroll
                    for (int r = 0; r < 16; r++) {
                        if ((r & rj) == 0) {
                            int r2 = r | rj;
                            bool asc = (r & km) != 0;
                            float a = v[r], bb = v[r2];
                            float lo = fminf(a, bb), hi = fmaxf(a, bb);
                            v[r]  = asc ? lo : hi;
                            v[r2] = asc ? hi : lo;
                        }
                    }
                } else {
                    #pragma unroll
                    for (int r = 0; r < 16; r++) {
                        int i = (r << 5) | lane;
                        bool asc   = (i & k) != 0;
                        bool lower = (lane & j) == 0;
                        float other = __shfl_xor_sync(0xffffffffu, v[r], j);
                        bool takeMin = (lower == asc);
                        v[r] = takeMin ? fminf(v[r], other) : fmaxf(v[r], other);
                    }
                }
            }
        }

        const float* wrow = g_wtab + c * NPOS;
        float s = 0.0f;
        #pragma unroll
        for (int r = 0; r < 16; r++) s += v[r] * wrow[r * 32 + lane];
        #pragma unroll
        for (int o = 16; o > 0; o >>= 1) s += __shfl_xor_sync(0xffffffffu, s, o);
        if (lane == 0) out[b * 129 + c] = s;
    }
}

// ---------------- launch ----------------
extern "C" void kernel_launch(void* const* d_in, const int* in_sizes, int n_in,
                              void* d_out, int out_size)
{
    (void)in_sizes; (void)n_in; (void)out_size;
    const float* x    = (const float*)d_in[0];
    const float* mask = (const float*)d_in[1];
    const float* w1   = (const float*)d_in[2];
    const float* b1   = (const float*)d_in[3];
    const float* w2   = (const float*)d_in[4];
    const float* b2   = (const float*)d_in[5];
    const float* w3   = (const float*)d_in[6];
    const float* b3   = (const float*)d_in[7];
    const float* w4   = (const float*)d_in[8];
    const float* b4   = (const float*)d_in[9];
    const float* pw   = (const float*)d_in[10];
    float* out = (float*)d_out;

    prep_kernel<<<256, 256>>>(w2, w3, w4, pw);

    cudaFuncSetAttribute(mlp_kernel, cudaFuncAttributeMaxDynamicSharedMemorySize, SM_TOTAL);
    dim3 grid(NPOS / MT, BATCH);
    mlp_kernel<<<grid, 256, SM_TOTAL>>>(x, mask, w1, b1, b2, b3, b4);

    sortpool_kernel<<<BATCH, 256>>>(mask, out);
}

// round 7
// speedup vs baseline: 2.3065x; 1.1581x over previous
#include <cuda_runtime.h>
#include <cuda_bf16.h>
#include <cstdint>

#define BATCH 1024
#define CIN   5
#define NPOS  512
#define DIM   256
#define C4    128
#define MT    128            // positions per CTA
#define AST   264            // act smem row stride (bf16): 132 words -> conflict-free
#define NTHR  512

// smem byte offsets
#define SM_XS    0                       // 5*128 f32 = 2560
#define SM_MK    2560                    // 128 f32 = 512
#define SM_BIAS  3072                    // 896 f32 = 3584
#define SM_ACT   6656                    // 2 act buffers (in-place across layers)
#define SM_AHI   (SM_ACT)                // 128*264*2 = 67584
#define SM_ALO   (SM_ACT + 67584)
#define SM_WBUF  (SM_ACT + 135168)       // double-buffered weight chunks (fragment-packed)
#define WBUF_SZ  32768
#define SM_TOTAL (SM_WBUF + 2 * WBUF_SZ) // 207360 bytes

// per-chunk byte sizes (32 K-cols, fragment-packed hi+lo: 16B per (ks,c,t))
#define CHB_256  (2 * 256 * 4 * 16)      // 32768
#define CHB_128  (2 * 128 * 4 * 16)      // 16384

// ---------------- device scratch ----------------
__device__ float g_h[(size_t)BATCH * C4 * NPOS];       // 256 MB masked activations
__device__ float g_wtab[C4 * NPOS];
// fragment-packed weights per 32-K chunk: record[(kc*2+ks)*C + c][t] = 16B:
//   { hi(K0),hi(K0+1),hi(K0+8),hi(K0+9), lo(K0),lo(K0+1),lo(K0+8),lo(K0+9) }, K0 = kc*32+ks*16+t*2
__device__ __align__(16) __nv_bfloat16 g_W2p[8 * 2 * 256 * 4 * 8];
__device__ __align__(16) __nv_bfloat16 g_W3p[8 * 2 * 256 * 4 * 8];
__device__ __align__(16) __nv_bfloat16 g_W4p[8 * 2 * 128 * 4 * 8];

// ---------------- helpers ----------------
__device__ __forceinline__ uint32_t smem_u32(const void* p) {
    uint32_t a;
    asm("{ .reg .u64 t; cvta.to.shared.u64 t, %1; cvt.u32.u64 %0, t; }" : "=r"(a) : "l"(p));
    return a;
}

__device__ __forceinline__ void mma16816(float* d, const unsigned* a, const unsigned* b) {
    asm volatile(
        "mma.sync.aligned.m16n8k16.row.col.f32.bf16.bf16.f32 "
        "{%0,%1,%2,%3}, {%4,%5,%6,%7}, {%8,%9}, {%0,%1,%2,%3};"
        : "+f"(d[0]), "+f"(d[1]), "+f"(d[2]), "+f"(d[3])
        : "r"(a[0]), "r"(a[1]), "r"(a[2]), "r"(a[3]), "r"(b[0]), "r"(b[1]));
}

__device__ __forceinline__ void split2(float a, float b, unsigned& hi, unsigned& lo) {
    __nv_bfloat16 ha = __float2bfloat16_rn(a);
    __nv_bfloat16 hb = __float2bfloat16_rn(b);
    __nv_bfloat162 hp; hp.x = ha; hp.y = hb;
    hi = *(unsigned*)&hp;
    __nv_bfloat162 lp;
    lp.x = __float2bfloat16_rn(a - __bfloat162float(ha));
    lp.y = __float2bfloat16_rn(b - __bfloat162float(hb));
    lo = *(unsigned*)&lp;
}

// all 512 threads: async-copy one weight chunk into ring buffer `buf`
__device__ __forceinline__ void prefetch_chunk(char* smem, int buf, const char* src,
                                               int bytes, int tid)
{
    uint32_t dst = smem_u32(smem + SM_WBUF + buf * WBUF_SZ);
    #pragma unroll 4
    for (int off = tid * 16; off < bytes; off += NTHR * 16)
        asm volatile("cp.async.cg.shared.global [%0], [%1], 16;"
                     :: "r"(dst + off), "l"(src + off));
    asm volatile("cp.async.commit_group;" ::: "memory");
}

// ---------------- prep: fragment-pack weights (hi/lo), pool table ----------------
__device__ __forceinline__ void pack_rec(__nv_bfloat16* base, int rec, const float* w,
                                         int c, int ldw, int K0)
{
    __nv_bfloat16 v[8];
    #pragma unroll
    for (int u = 0; u < 4; u++) {
        int k = K0 + (u >> 1) * 8 + (u & 1);
        float f = w[c * ldw + k];
        v[u] = __float2bfloat16_rn(f);
        v[4 + u] = __float2bfloat16_rn(f - __bfloat162float(v[u]));
    }
    *(uint4*)&base[rec * 8] = *(uint4*)v;
}

__global__ void prep_kernel(const float* __restrict__ w2, const float* __restrict__ w3,
                            const float* __restrict__ w4, const float* __restrict__ pw)
{
    int i = blockIdx.x * blockDim.x + threadIdx.x;   // 65536 threads

    if (i < 16384) {   // W2 / W3: t, c(256), ks, kc
        int t = i & 3, c = (i >> 2) & 255, ks = (i >> 10) & 1, kc = (i >> 11) & 7;
        int K0 = kc * 32 + ks * 16 + t * 2;
        int rec = ((kc * 2 + ks) * 256 + c) * 4 + t;
        pack_rec(g_W2p, rec, w2, c, DIM, K0);
        pack_rec(g_W3p, rec, w3, c, DIM, K0);
    }
    if (i < 8192) {    // W4: t, c(128), ks, kc
        int t = i & 3, c = (i >> 2) & 127, ks = (i >> 9) & 1, kc = (i >> 10) & 7;
        int K0 = kc * 32 + ks * 16 + t * 2;
        int rec = ((kc * 2 + ks) * 128 + c) * 4 + t;
        pack_rec(g_W4p, rec, w4, c, DIM, K0);
    }

    // pool weight table (128 x 512)
    int ch = i >> 9, n = i & 511;
    float ratio = (float)n / 511.0f;
    float pos = 20.0f * ratio;
    float fidx = floorf(pos);
    int idx = (int)fidx;
    float frac = pos - fidx;
    int idx2 = idx + 1; if (idx2 > 20) idx2 = 20;
    g_wtab[i] = (1.0f - frac) * pw[ch * 21 + idx] + frac * pw[ch * 21 + idx2];
}

// ---------------- mma layer over 8 double-buffered 32-K chunks, 2 m-tiles/warp ----------------
template<int COUT, int NT>
__device__ __forceinline__ void layer_mma(
    char* smem, const __nv_bfloat16* __restrict__ wglob,
    const char* __restrict__ wnext, int next_bytes,
    const __nv_bfloat16* aHi, const __nv_bfloat16* aLo,
    float (*acc0)[4], float (*acc1)[4],
    int tid, int wm, int wn, int g, int t2)
{
    const int CHB = 2 * COUT * 4 * 16;
    const int tq = t2 >> 1;           // lane & 3
    #pragma unroll 1
    for (int kc = 0; kc < 8; kc++) {
        asm volatile("cp.async.wait_group 0;" ::: "memory");
        __syncthreads();
        if (kc < 7)
            prefetch_chunk(smem, (kc + 1) & 1, (const char*)wglob + (size_t)(kc + 1) * CHB, CHB, tid);
        else if (wnext)
            prefetch_chunk(smem, 0, wnext, next_bytes, tid);

        const uint4* wf = (const uint4*)(smem + SM_WBUF + (kc & 1) * WBUF_SZ);

        #pragma unroll
        for (int ks = 0; ks < 2; ks++) {
            const int kcol = ks * 16 + t2;
            const int acol = kc * 32 + kcol;
            const int row0 = wm * 32 + g;         // m-tile 0
            const int row1 = row0 + 16;           // m-tile 1
            unsigned ahi0[4], alo0[4], ahi1[4], alo1[4];
            ahi0[0] = *(const unsigned*)&aHi[(row0    ) * AST + acol    ];
            ahi0[1] = *(const unsigned*)&aHi[(row0 + 8) * AST + acol    ];
            ahi0[2] = *(const unsigned*)&aHi[(row0    ) * AST + acol + 8];
            ahi0[3] = *(const unsigned*)&aHi[(row0 + 8) * AST + acol + 8];
            alo0[0] = *(const unsigned*)&aLo[(row0    ) * AST + acol    ];
            alo0[1] = *(const unsigned*)&aLo[(row0 + 8) * AST + acol    ];
            alo0[2] = *(const unsigned*)&aLo[(row0    ) * AST + acol + 8];
            alo0[3] = *(const unsigned*)&aLo[(row0 + 8) * AST + acol + 8];
            ahi1[0] = *(const unsigned*)&aHi[(row1    ) * AST + acol    ];
            ahi1[1] = *(const unsigned*)&aHi[(row1 + 8) * AST + acol    ];
            ahi1[2] = *(const unsigned*)&aHi[(row1    ) * AST + acol + 8];
            ahi1[3] = *(const unsigned*)&aHi[(row1 + 8) * AST + acol + 8];
            alo1[0] = *(const unsigned*)&aLo[(row1    ) * AST + acol    ];
            alo1[1] = *(const unsigned*)&aLo[(row1 + 8) * AST + acol    ];
            alo1[2] = *(const unsigned*)&aLo[(row1    ) * AST + acol + 8];
            alo1[3] = *(const unsigned*)&aLo[(row1 + 8) * AST + acol + 8];
            #pragma unroll
            for (int n8 = 0; n8 < NT; n8++) {
                const int c = wn * (NT * 8) + n8 * 8 + g;
                uint4 v = wf[(ks * COUT + c) * 4 + tq];   // one LDS.128: bh + bl
                unsigned bh[2] = { v.x, v.y };
                unsigned bl[2] = { v.z, v.w };
                mma16816(acc0[n8], ahi0, bh);
                mma16816(acc0[n8], ahi0, bl);
                mma16816(acc0[n8], alo0, bh);
                mma16816(acc1[n8], ahi1, bh);
                mma16816(acc1[n8], ahi1, bl);
                mma16816(acc1[n8], alo1, bh);
            }
        }
    }
}

// ---------------- fused 4-layer MLP, 128 positions per CTA, 512 threads ----------------
__global__ void __launch_bounds__(NTHR, 1)
mlp_kernel(const float* __restrict__ x, const float* __restrict__ mask,
           const float* __restrict__ w1,
           const float* __restrict__ b1, const float* __restrict__ b2,
           const float* __restrict__ b3, const float* __restrict__ b4)
{
    extern __shared__ char smem[];
    const int tid  = threadIdx.x;
    const int lane = tid & 31;
    const int warp = tid >> 5;       // 0..15
    const int wm   = warp & 3;       // 32-row group
    const int wn   = warp >> 2;      // 0..3 n-group
    const int g    = lane >> 2;
    const int t2   = (lane & 3) * 2;
    const int b    = blockIdx.y;
    const int n0   = blockIdx.x * MT;

    // kick off layer-2 chunk 0 immediately (covered by layer-1 scalar work)
    prefetch_chunk(smem, 0, (const char*)g_W2p, CHB_256, tid);

    float* xs    = (float*)(smem + SM_XS);
    float* mkS   = (float*)(smem + SM_MK);
    float* sBias = (float*)(smem + SM_BIAS);
    __nv_bfloat16* aHi = (__nv_bfloat16*)(smem + SM_AHI);
    __nv_bfloat16* aLo = (__nv_bfloat16*)(smem + SM_ALO);

    // stage x tile, mask, biases
    for (int i = tid; i < CIN * MT; i += NTHR) {
        int k = i / MT, n = i % MT;
        xs[k * MT + n] = x[((size_t)b * CIN + k) * NPOS + n0 + n];
    }
    if (tid < MT) mkS[tid] = mask[(size_t)b * NPOS + n0 + tid] * (1.0f / NPOS);
    for (int i = tid; i < 896; i += NTHR) {
        float v;
        if      (i < 256) v = b1[i];
        else if (i < 512) v = b2[i - 256];
        else if (i < 768) v = b3[i - 512];
        else              v = b4[i - 768];
        sBias[i] = v;
    }
    __syncthreads();

    // ---- layer 1 (scalar, K=5): thread -> 2 channels x 32 positions
    {
        const int ch0 = (tid & 127) * 2;
        const int nh  = tid >> 7;            // 0..3
        float wr0[CIN], wr1[CIN];
        #pragma unroll
        for (int k = 0; k < CIN; k++) {
            wr0[k] = __ldg(&w1[ch0 * CIN + k]);
            wr1[k] = __ldg(&w1[(ch0 + 1) * CIN + k]);
        }
        const float bb0 = sBias[ch0], bb1 = sBias[ch0 + 1];
        #pragma unroll 4
        for (int nl = 0; nl < 32; nl++) {
            const int n = nh * 32 + nl;
            float a0 = bb0, a1 = bb1;
            #pragma unroll
            for (int k = 0; k < CIN; k++) {
                float xv = xs[k * MT + n];
                a0 += xv * wr0[k];
                a1 += xv * wr1[k];
            }
            a0 = fmaxf(a0, 0.0f); a1 = fmaxf(a1, 0.0f);
            unsigned hi, lo;
            split2(a0, a1, hi, lo);
            *(unsigned*)&aHi[n * AST + ch0] = hi;
            *(unsigned*)&aLo[n * AST + ch0] = lo;
        }
    }
    __syncthreads();

    float acc0[8][4], acc1[8][4];

    // ---- layers 2 and 3 (in-place act update)
    #pragma unroll 1
    for (int L = 0; L < 2; L++) {
        #pragma unroll
        for (int i = 0; i < 8; i++) {
            acc0[i][0]=acc0[i][1]=acc0[i][2]=acc0[i][3]=0.0f;
            acc1[i][0]=acc1[i][1]=acc1[i][2]=acc1[i][3]=0.0f;
        }
        const __nv_bfloat16* wg = (L == 0) ? g_W2p : g_W3p;
        const char* wnxt = (L == 0) ? (const char*)g_W3p : (const char*)g_W4p;
        const int nb = (L == 0) ? CHB_256 : CHB_128;
        layer_mma<256, 8>(smem, wg, wnxt, nb, aHi, aLo, acc0, acc1, tid, wm, wn, g, t2);
        __syncthreads();                 // all MMA reads done before in-place overwrite
        const float* lb = sBias + 256 * (L + 1);
        #pragma unroll
        for (int n8 = 0; n8 < 8; n8++) {
            const int col = wn * 64 + n8 * 8 + t2;
            const float bb0 = lb[col], bb1 = lb[col + 1];
            #pragma unroll
            for (int half = 0; half < 2; half++) {
                const int r0 = wm * 32 + g + half * 8;
                float v0 = fmaxf(acc0[n8][half * 2 + 0] + bb0, 0.0f);
                float v1 = fmaxf(acc0[n8][half * 2 + 1] + bb1, 0.0f);
                unsigned hi, lo;
                split2(v0, v1, hi, lo);
                *(unsigned*)&aHi[r0 * AST + col] = hi;
                *(unsigned*)&aLo[r0 * AST + col] = lo;
                const int r1 = r0 + 16;
                v0 = fmaxf(acc1[n8][half * 2 + 0] + bb0, 0.0f);
                v1 = fmaxf(acc1[n8][half * 2 + 1] + bb1, 0.0f);
                split2(v0, v1, hi, lo);
                *(unsigned*)&aHi[r1 * AST + col] = hi;
                *(unsigned*)&aLo[r1 * AST + col] = lo;
            }
        }
        __syncthreads();
    }

    // ---- layer 4: A -> transpose buffer (f32, over act area) -> g_h
    #pragma unroll
    for (int i = 0; i < 4; i++) {
        acc0[i][0]=acc0[i][1]=acc0[i][2]=acc0[i][3]=0.0f;
        acc1[i][0]=acc1[i][1]=acc1[i][2]=acc1[i][3]=0.0f;
    }
    layer_mma<128, 4>(smem, g_W4p, (const char*)0, 0, aHi, aLo, acc0, acc1, tid, wm, wn, g, t2);

    float* sT = (float*)(smem + SM_ACT);    // [128 c][132 n] f32, overlays act buffers
    __syncthreads();                        // all MMA reads of acts done
    #pragma unroll
    for (int n8 = 0; n8 < 4; n8++) {
        const int c = wn * 32 + n8 * 8 + t2;
        const float bb0 = sBias[768 + c], bb1 = sBias[768 + c + 1];
        #pragma unroll
        for (int half = 0; half < 2; half++) {
            const int n0r = wm * 32 + g + half * 8;
            sT[(c    ) * 132 + n0r] = acc0[n8][half * 2 + 0] + bb0;
            sT[(c + 1) * 132 + n0r] = acc0[n8][half * 2 + 1] + bb1;
            sT[(c    ) * 132 + n0r + 16] = acc1[n8][half * 2 + 0] + bb0;
            sT[(c + 1) * 132 + n0r + 16] = acc1[n8][half * 2 + 1] + bb1;
        }
    }
    __syncthreads();
    {
        const int c   = tid >> 2;           // 0..127
        const int seg = tid & 3;            // 32-position segment
        float* dst = g_h + (((size_t)b * C4 + c) << 9) + n0 + seg * 32;
        #pragma unroll
        for (int i = 0; i < 8; i++) {
            const int nn = seg * 32 + i * 4;
            float4 v = *(float4*)&sT[c * 132 + nn];
            v.x *= mkS[nn + 0]; v.y *= mkS[nn + 1];
            v.z *= mkS[nn + 2]; v.w *= mkS[nn + 3];
            *(float4*)&dst[i * 4] = v;
        }
    }
}

// ---------------- warp-register bitonic sort (desc, 512) + weighted pool ----------------
__global__ void __launch_bounds__(256)
sortpool_kernel(const float* __restrict__ mask, float* __restrict__ out)
{
    const int b    = blockIdx.x >> 1;
    const int hf   = blockIdx.x & 1;
    const int tid  = threadIdx.x;
    const int lane = tid & 31;
    const int warp = tid >> 5;
    __shared__ float sred[8];

    // size feature: mean(mask) * 4 (half 0 only)
    if (hf == 0) {
        float s = mask[(size_t)b * NPOS + tid] + mask[(size_t)b * NPOS + tid + 256];
        #pragma unroll
        for (int o = 16; o > 0; o >>= 1) s += __shfl_xor_sync(0xffffffffu, s, o);
        if (lane == 0) sred[warp] = s;
        __syncthreads();
        if (tid == 0) {
            float t = 0.0f;
            #pragma unroll
            for (int i = 0; i < 8; i++) t += sred[i];
            out[b * 129 + 128] = t * (4.0f / NPOS);
        }
    }

    for (int c = hf * 64 + warp; c < hf * 64 + 64; c += 8) {
        const float* row = g_h + (((size_t)b * C4 + c) << 9);
        float v[16];
        #pragma unroll
        for (int r = 0; r < 16; r++) v[r] = row[r * 32 + lane];

        #pragma unroll 1
        for (int k = 2; k <= 512; k <<= 1) {
            #pragma unroll 1
            for (int j = k >> 1; j > 0; j >>= 1) {
                if (j >= 32) {
                    int rj = j >> 5, km = k >> 5;
                    #pragma unroll
                    for (int r = 0; r < 16; r++) {
                        if ((r & rj) == 0) {
                            int r2 = r | rj;
                            bool asc = (r & km) != 0;
                            float a = v[r], bb = v[r2];
                            float lo = fminf(a, bb), hi = fmaxf(a, bb);
                            v[r]  = asc ? lo : hi;
                            v[r2] = asc ? hi : lo;
                        }
                    }
                } else {
                    #pragma unroll
                    for (int r = 0; r < 16; r++) {
                        int i = (r << 5) | lane;
                        bool asc   = (i & k) != 0;
                        bool lower = (lane & j) == 0;
                        float other = __shfl_xor_sync(0xffffffffu, v[r], j);
                        bool takeMin = (lower == asc);
                        v[r] = takeMin ? fminf(v[r], other) : fmaxf(v[r], other);
                    }
                }
            }
        }

        const float* wrow = g_wtab + c * NPOS;
        float s = 0.0f;
        #pragma unroll
        for (int r = 0; r < 16; r++) s += v[r] * wrow[r * 32 + lane];
        #pragma unroll
        for (int o = 16; o > 0; o >>= 1) s += __shfl_xor_sync(0xffffffffu, s, o);
        if (lane == 0) out[b * 129 + c] = s;
    }
}

// ---------------- launch ----------------
extern "C" void kernel_launch(void* const* d_in, const int* in_sizes, int n_in,
                              void* d_out, int out_size)
{
    (void)in_sizes; (void)n_in; (void)out_size;
    const float* x    = (const float*)d_in[0];
    const float* mask = (const float*)d_in[1];
    const float* w1   = (const float*)d_in[2];
    const float* b1   = (const float*)d_in[3];
    const float* w2   = (const float*)d_in[4];
    const float* b2   = (const float*)d_in[5];
    const float* w3   = (const float*)d_in[6];
    const float* b3   = (const float*)d_in[7];
    const float* w4   = (const float*)d_in[8];
    const float* b4   = (const float*)d_in[9];
    const float* pw   = (const float*)d_in[10];
    float* out = (float*)d_out;

    prep_kernel<<<256, 256>>>(w2, w3, w4, pw);

    cudaFuncSetAttribute(mlp_kernel, cudaFuncAttributeMaxDynamicSharedMemorySize, SM_TOTAL);
    dim3 grid(NPOS / MT, BATCH);
    mlp_kernel<<<grid, NTHR, SM_TOTAL>>>(x, mask, w1, b1, b2, b3, b4);

    sortpool_kernel<<<BATCH * 2, 256>>>(mask, out);
}

// round 8
// speedup vs baseline: 2.3477x; 1.0179x over previous
#include <cuda_runtime.h>
#include <cuda_bf16.h>
#include <cstdint>

#define BATCH 1024
#define CIN   5
#define NPOS  512
#define DIM   256
#define C4    128
#define MT    64             // positions per CTA
#define AST   264            // act smem row stride (bf16): 132 words -> conflict-free
#define NTHR  256

// smem byte offsets (single CTA footprint ~105.5 KB -> 2 CTAs/SM)
#define SM_XS    0                       // 5*64 f32 = 1280
#define SM_MK    1280                    // 64 f32 = 256
#define SM_BIAS  1536                    // 896 f32 = 3584
#define SM_ACT   5120                    // 2 act buffers (in-place across layers)
#define SM_AHI   (SM_ACT)                // 64*264*2 = 33792
#define SM_ALO   (SM_ACT + 33792)
#define SM_WBUF  (SM_ACT + 67584)        // SINGLE weight chunk buffer
#define WBUF_SZ  32768
#define SM_TOTAL (SM_WBUF + WBUF_SZ)     // 105472 bytes

// per-chunk byte sizes (32 K-cols, fragment-packed hi+lo: 16B per (ks,c,t))
#define CHB_256  (2 * 256 * 4 * 16)      // 32768
#define CHB_128  (2 * 128 * 4 * 16)      // 16384

// ---------------- device scratch ----------------
__device__ float g_h[(size_t)BATCH * C4 * NPOS];       // 256 MB masked activations
__device__ float g_wtab[C4 * NPOS];
// fragment-packed weights per 32-K chunk: record[(kc*2+ks)*C + c][t] = 16B:
//   { hi(K0),hi(K0+1),hi(K0+8),hi(K0+9), lo(K0),lo(K0+1),lo(K0+8),lo(K0+9) }, K0 = kc*32+ks*16+t*2
__device__ __align__(16) __nv_bfloat16 g_W2p[8 * 2 * 256 * 4 * 8];
__device__ __align__(16) __nv_bfloat16 g_W3p[8 * 2 * 256 * 4 * 8];
__device__ __align__(16) __nv_bfloat16 g_W4p[8 * 2 * 128 * 4 * 8];

// ---------------- helpers ----------------
__device__ __forceinline__ uint32_t smem_u32(const void* p) {
    uint32_t a;
    asm("{ .reg .u64 t; cvta.to.shared.u64 t, %1; cvt.u32.u64 %0, t; }" : "=r"(a) : "l"(p));
    return a;
}

__device__ __forceinline__ void mma16816(float* d, const unsigned* a, const unsigned* b) {
    asm volatile(
        "mma.sync.aligned.m16n8k16.row.col.f32.bf16.bf16.f32 "
        "{%0,%1,%2,%3}, {%4,%5,%6,%7}, {%8,%9}, {%0,%1,%2,%3};"
        : "+f"(d[0]), "+f"(d[1]), "+f"(d[2]), "+f"(d[3])
        : "r"(a[0]), "r"(a[1]), "r"(a[2]), "r"(a[3]), "r"(b[0]), "r"(b[1]));
}

__device__ __forceinline__ void split2(float a, float b, unsigned& hi, unsigned& lo) {
    __nv_bfloat16 ha = __float2bfloat16_rn(a);
    __nv_bfloat16 hb = __float2bfloat16_rn(b);
    __nv_bfloat162 hp; hp.x = ha; hp.y = hb;
    hi = *(unsigned*)&hp;
    __nv_bfloat162 lp;
    lp.x = __float2bfloat16_rn(a - __bfloat162float(ha));
    lp.y = __float2bfloat16_rn(b - __bfloat162float(hb));
    lo = *(unsigned*)&lp;
}

// all 256 threads: async-copy one weight chunk into the single ring buffer
__device__ __forceinline__ void prefetch_chunk(char* smem, const char* src,
                                               int bytes, int tid)
{
    uint32_t dst = smem_u32(smem + SM_WBUF);
    #pragma unroll 4
    for (int off = tid * 16; off < bytes; off += NTHR * 16)
        asm volatile("cp.async.cg.shared.global [%0], [%1], 16;"
                     :: "r"(dst + off), "l"(src + off));
    asm volatile("cp.async.commit_group;" ::: "memory");
}

// ---------------- prep: fragment-pack weights (hi/lo), pool table ----------------
__device__ __forceinline__ void pack_rec(__nv_bfloat16* base, int rec, const float* w,
                                         int c, int ldw, int K0)
{
    __nv_bfloat16 v[8];
    #pragma unroll
    for (int u = 0; u < 4; u++) {
        int k = K0 + (u >> 1) * 8 + (u & 1);
        float f = w[c * ldw + k];
        v[u] = __float2bfloat16_rn(f);
        v[4 + u] = __float2bfloat16_rn(f - __bfloat162float(v[u]));
    }
    *(uint4*)&base[rec * 8] = *(uint4*)v;
}

__global__ void prep_kernel(const float* __restrict__ w2, const float* __restrict__ w3,
                            const float* __restrict__ w4, const float* __restrict__ pw)
{
    int i = blockIdx.x * blockDim.x + threadIdx.x;   // 65536 threads

    if (i < 16384) {   // W2 / W3: t, c(256), ks, kc
        int t = i & 3, c = (i >> 2) & 255, ks = (i >> 10) & 1, kc = (i >> 11) & 7;
        int K0 = kc * 32 + ks * 16 + t * 2;
        int rec = ((kc * 2 + ks) * 256 + c) * 4 + t;
        pack_rec(g_W2p, rec, w2, c, DIM, K0);
        pack_rec(g_W3p, rec, w3, c, DIM, K0);
    }
    if (i < 8192) {    // W4: t, c(128), ks, kc
        int t = i & 3, c = (i >> 2) & 127, ks = (i >> 9) & 1, kc = (i >> 10) & 7;
        int K0 = kc * 32 + ks * 16 + t * 2;
        int rec = ((kc * 2 + ks) * 128 + c) * 4 + t;
        pack_rec(g_W4p, rec, w4, c, DIM, K0);
    }

    // pool weight table (128 x 512)
    int ch = i >> 9, n = i & 511;
    float ratio = (float)n / 511.0f;
    float pos = 20.0f * ratio;
    float fidx = floorf(pos);
    int idx = (int)fidx;
    float frac = pos - fidx;
    int idx2 = idx + 1; if (idx2 > 20) idx2 = 20;
    g_wtab[i] = (1.0f - frac) * pw[ch * 21 + idx] + frac * pw[ch * 21 + idx2];
}

// ---------------- mma layer over 8 single-buffered 32-K chunks, 2 m-tiles/warp ----------------
// Load->compute serialization within a CTA is hidden by the co-resident CTA's compute.
template<int COUT, int NT>
__device__ __forceinline__ void layer_mma(
    char* smem, const __nv_bfloat16* __restrict__ wglob,
    const char* __restrict__ wnext, int next_bytes,
    const __nv_bfloat16* aHi, const __nv_bfloat16* aLo,
    float (*acc0)[4], float (*acc1)[4],
    int tid, int wm, int wn, int g, int t2)
{
    const int CHB = 2 * COUT * 4 * 16;
    const int tq = t2 >> 1;           // lane & 3
    #pragma unroll 1
    for (int kc = 0; kc < 8; kc++) {
        asm volatile("cp.async.wait_group 0;" ::: "memory");
        __syncthreads();               // chunk kc resident & visible

        const uint4* wf = (const uint4*)(smem + SM_WBUF);

        #pragma unroll
        for (int ks = 0; ks < 2; ks++) {
            const int kcol = ks * 16 + t2;
            const int acol = kc * 32 + kcol;
            const int row0 = wm * 32 + g;         // m-tile 0
            const int row1 = row0 + 16;           // m-tile 1
            unsigned ahi0[4], alo0[4], ahi1[4], alo1[4];
            ahi0[0] = *(const unsigned*)&aHi[(row0    ) * AST + acol    ];
            ahi0[1] = *(const unsigned*)&aHi[(row0 + 8) * AST + acol    ];
            ahi0[2] = *(const unsigned*)&aHi[(row0    ) * AST + acol + 8];
            ahi0[3] = *(const unsigned*)&aHi[(row0 + 8) * AST + acol + 8];
            alo0[0] = *(const unsigned*)&aLo[(row0    ) * AST + acol    ];
            alo0[1] = *(const unsigned*)&aLo[(row0 + 8) * AST + acol    ];
            alo0[2] = *(const unsigned*)&aLo[(row0    ) * AST + acol + 8];
            alo0[3] = *(const unsigned*)&aLo[(row0 + 8) * AST + acol + 8];
            ahi1[0] = *(const unsigned*)&aHi[(row1    ) * AST + acol    ];
            ahi1[1] = *(const unsigned*)&aHi[(row1 + 8) * AST + acol    ];
            ahi1[2] = *(const unsigned*)&aHi[(row1    ) * AST + acol + 8];
            ahi1[3] = *(const unsigned*)&aHi[(row1 + 8) * AST + acol + 8];
            alo1[0] = *(const unsigned*)&aLo[(row1    ) * AST + acol    ];
            alo1[1] = *(const unsigned*)&aLo[(row1 + 8) * AST + acol    ];
            alo1[2] = *(const unsigned*)&aLo[(row1    ) * AST + acol + 8];
            alo1[3] = *(const unsigned*)&aLo[(row1 + 8) * AST + acol + 8];
            #pragma unroll
            for (int n8 = 0; n8 < NT; n8++) {
                const int c = wn * (NT * 8) + n8 * 8 + g;
                uint4 v = wf[(ks * COUT + c) * 4 + tq];   // one LDS.128: bh + bl
                unsigned bh[2] = { v.x, v.y };
                unsigned bl[2] = { v.z, v.w };
                mma16816(acc0[n8], ahi0, bh);
                mma16816(acc0[n8], ahi0, bl);
                mma16816(acc0[n8], alo0, bh);
                mma16816(acc1[n8], ahi1, bh);
                mma16816(acc1[n8], ahi1, bl);
                mma16816(acc1[n8], alo1, bh);
            }
        }
        __syncthreads();               // all reads of wbuf done before refill
        if (kc < 7)
            prefetch_chunk(smem, (const char*)wglob + (size_t)(kc + 1) * CHB, CHB, tid);
        else if (wnext)
            prefetch_chunk(smem, wnext, next_bytes, tid);   // hidden by epilogue
    }
}

// ---------------- fused 4-layer MLP, 64 positions per CTA, 256 threads, 2 CTAs/SM ----------------
__global__ void __launch_bounds__(NTHR, 2)
mlp_kernel(const float* __restrict__ x, const float* __restrict__ mask,
           const float* __restrict__ w1,
           const float* __restrict__ b1, const float* __restrict__ b2,
           const float* __restrict__ b3, const float* __restrict__ b4)
{
    extern __shared__ char smem[];
    const int tid  = threadIdx.x;
    const int lane = tid & 31;
    const int warp = tid >> 5;       // 0..7
    const int wm   = warp & 1;       // 32-row group
    const int wn   = warp >> 1;      // 0..3 n-group
    const int g    = lane >> 2;
    const int t2   = (lane & 3) * 2;
    const int b    = blockIdx.y;
    const int n0   = blockIdx.x * MT;

    // kick off layer-2 chunk 0 immediately (covered by layer-1 scalar work)
    prefetch_chunk(smem, (const char*)g_W2p, CHB_256, tid);

    float* xs    = (float*)(smem + SM_XS);
    float* mkS   = (float*)(smem + SM_MK);
    float* sBias = (float*)(smem + SM_BIAS);
    __nv_bfloat16* aHi = (__nv_bfloat16*)(smem + SM_AHI);
    __nv_bfloat16* aLo = (__nv_bfloat16*)(smem + SM_ALO);

    // stage x tile, mask, biases
    for (int i = tid; i < CIN * MT; i += NTHR) {
        int k = i / MT, n = i % MT;
        xs[k * MT + n] = x[((size_t)b * CIN + k) * NPOS + n0 + n];
    }
    if (tid < MT) mkS[tid] = mask[(size_t)b * NPOS + n0 + tid] * (1.0f / NPOS);
    for (int i = tid; i < 896; i += NTHR) {
        float v;
        if      (i < 256) v = b1[i];
        else if (i < 512) v = b2[i - 256];
        else if (i < 768) v = b3[i - 512];
        else              v = b4[i - 768];
        sBias[i] = v;
    }
    __syncthreads();

    // ---- layer 1 (scalar, K=5): thread -> 2 channels x 32 positions
    {
        const int ch0 = (tid & 127) * 2;
        const int nh  = tid >> 7;            // 0..1
        float wr0[CIN], wr1[CIN];
        #pragma unroll
        for (int k = 0; k < CIN; k++) {
            wr0[k] = __ldg(&w1[ch0 * CIN + k]);
            wr1[k] = __ldg(&w1[(ch0 + 1) * CIN + k]);
        }
        const float bb0 = sBias[ch0], bb1 = sBias[ch0 + 1];
        #pragma unroll 4
        for (int nl = 0; nl < 32; nl++) {
            const int n = nh * 32 + nl;
            float a0 = bb0, a1 = bb1;
            #pragma unroll
            for (int k = 0; k < CIN; k++) {
                float xv = xs[k * MT + n];
                a0 += xv * wr0[k];
                a1 += xv * wr1[k];
            }
            a0 = fmaxf(a0, 0.0f); a1 = fmaxf(a1, 0.0f);
            unsigned hi, lo;
            split2(a0, a1, hi, lo);
            *(unsigned*)&aHi[n * AST + ch0] = hi;
            *(unsigned*)&aLo[n * AST + ch0] = lo;
        }
    }
    __syncthreads();

    float acc0[8][4], acc1[8][4];

    // ---- layers 2 and 3 (in-place act update)
    #pragma unroll 1
    for (int L = 0; L < 2; L++) {
        #pragma unroll
        for (int i = 0; i < 8; i++) {
            acc0[i][0]=acc0[i][1]=acc0[i][2]=acc0[i][3]=0.0f;
            acc1[i][0]=acc1[i][1]=acc1[i][2]=acc1[i][3]=0.0f;
        }
        const __nv_bfloat16* wg = (L == 0) ? g_W2p : g_W3p;
        const char* wnxt = (L == 0) ? (const char*)g_W3p : (const char*)g_W4p;
        const int nb = (L == 0) ? CHB_256 : CHB_128;
        layer_mma<256, 8>(smem, wg, wnxt, nb, aHi, aLo, acc0, acc1, tid, wm, wn, g, t2);
        // next-layer chunk 0 is loading during this epilogue
        const float* lb = sBias + 256 * (L + 1);
        #pragma unroll
        for (int n8 = 0; n8 < 8; n8++) {
            const int col = wn * 64 + n8 * 8 + t2;
            const float bb0 = lb[col], bb1 = lb[col + 1];
            #pragma unroll
            for (int half = 0; half < 2; half++) {
                const int r0 = wm * 32 + g + half * 8;
                float v0 = fmaxf(acc0[n8][half * 2 + 0] + bb0, 0.0f);
                float v1 = fmaxf(acc0[n8][half * 2 + 1] + bb1, 0.0f);
                unsigned hi, lo;
                split2(v0, v1, hi, lo);
                *(unsigned*)&aHi[r0 * AST + col] = hi;
                *(unsigned*)&aLo[r0 * AST + col] = lo;
                const int r1 = r0 + 16;
                v0 = fmaxf(acc1[n8][half * 2 + 0] + bb0, 0.0f);
                v1 = fmaxf(acc1[n8][half * 2 + 1] + bb1, 0.0f);
                split2(v0, v1, hi, lo);
                *(unsigned*)&aHi[r1 * AST + col] = hi;
                *(unsigned*)&aLo[r1 * AST + col] = lo;
            }
        }
        __syncthreads();
    }

    // ---- layer 4: A -> transpose buffer (f32, over act area) -> g_h
    #pragma unroll
    for (int i = 0; i < 4; i++) {
        acc0[i][0]=acc0[i][1]=acc0[i][2]=acc0[i][3]=0.0f;
        acc1[i][0]=acc1[i][1]=acc1[i][2]=acc1[i][3]=0.0f;
    }
    layer_mma<128, 4>(smem, g_W4p, (const char*)0, 0, aHi, aLo, acc0, acc1, tid, wm, wn, g, t2);

    float* sT = (float*)(smem + SM_ACT);    // [128 c][68 n] f32, overlays act buffers
    __syncthreads();                        // all MMA reads of acts done
    #pragma unroll
    for (int n8 = 0; n8 < 4; n8++) {
        const int c = wn * 32 + n8 * 8 + t2;
        const float bb0 = sBias[768 + c], bb1 = sBias[768 + c + 1];
        #pragma unroll
        for (int half = 0; half < 2; half++) {
            const int n0r = wm * 32 + g + half * 8;
            sT[(c    ) * 68 + n0r] = acc0[n8][half * 2 + 0] + bb0;
            sT[(c + 1) * 68 + n0r] = acc0[n8][half * 2 + 1] + bb1;
            sT[(c    ) * 68 + n0r + 16] = acc1[n8][half * 2 + 0] + bb0;
            sT[(c + 1) * 68 + n0r + 16] = acc1[n8][half * 2 + 1] + bb1;
        }
    }
    __syncthreads();
    {
        const int c   = tid >> 1;           // 0..127
        const int seg = tid & 1;            // 32-position segment
        float* dst = g_h + (((size_t)b * C4 + c) << 9) + n0 + seg * 32;
        #pragma unroll
        for (int i = 0; i < 8; i++) {
            const int nn = seg * 32 + i * 4;
            float4 v = *(float4*)&sT[c * 68 + nn];
            v.x *= mkS[nn + 0]; v.y *= mkS[nn + 1];
            v.z *= mkS[nn + 2]; v.w *= mkS[nn + 3];
            *(float4*)&dst[i * 4] = v;
        }
    }
}

// ---------------- warp-register bitonic sort (desc, 512) + weighted pool ----------------
__global__ void __launch_bounds__(256)
sortpool_kernel(const float* __restrict__ mask, float* __restrict__ out)
{
    const int b    = blockIdx.x >> 1;
    const int hf   = blockIdx.x & 1;
    const int tid  = threadIdx.x;
    const int lane = tid & 31;
    const int warp = tid >> 5;
    __shared__ float sred[8];

    // size feature: mean(mask) * 4 (half 0 only)
    if (hf == 0) {
        float s = mask[(size_t)b * NPOS + tid] + mask[(size_t)b * NPOS + tid + 256];
        #pragma unroll
        for (int o = 16; o > 0; o >>= 1) s += __shfl_xor_sync(0xffffffffu, s, o);
        if (lane == 0) sred[warp] = s;
        __syncthreads();
        if (tid == 0) {
            float t = 0.0f;
            #pragma unroll
            for (int i = 0; i < 8; i++) t += sred[i];
            out[b * 129 + 128] = t * (4.0f / NPOS);
        }
    }

    for (int c = hf * 64 + warp; c < hf * 64 + 64; c += 8) {
        const float* row = g_h + (((size_t)b * C4 + c) << 9);
        float v[16];
        #pragma unroll
        for (int r = 0; r < 16; r++) v[r] = row[r * 32 + lane];

        #pragma unroll 1
        for (int k = 2; k <= 512; k <<= 1) {
            #pragma unroll 1
            for (int j = k >> 1; j > 0; j >>= 1) {
                if (j >= 32) {
                    int rj = j >> 5, km = k >> 5;
                    #pragma unroll
                    for (int r = 0; r < 16; r++) {
                        if ((r & rj) == 0) {
                            int r2 = r | rj;
                            bool asc = (r & km) != 0;
                            float a = v[r], bb = v[r2];
                            float lo = fminf(a, bb), hi = fmaxf(a, bb);
                            v[r]  = asc ? lo : hi;
                            v[r2] = asc ? hi : lo;
                        }
                    }
                } else {
                    #pragma unroll
                    for (int r = 0; r < 16; r++) {
                        int i = (r << 5) | lane;
                        bool asc   = (i & k) != 0;
                        bool lower = (lane & j) == 0;
                        float other = __shfl_xor_sync(0xffffffffu, v[r], j);
                        bool takeMin = (lower == asc);
                        v[r] = takeMin ? fminf(v[r], other) : fmaxf(v[r], other);
                    }
                }
            }
        }

        const float* wrow = g_wtab + c * NPOS;
        float s = 0.0f;
        #pragma unroll
        for (int r = 0; r < 16; r++) s += v[r] * wrow[r * 32 + lane];
        #pragma unroll
        for (int o = 16; o > 0; o >>= 1) s += __shfl_xor_sync(0xffffffffu, s, o);
        if (lane == 0) out[b * 129 + c] = s;
    }
}

// ---------------- launch ----------------
extern "C" void kernel_launch(void* const* d_in, const int* in_sizes, int n_in,
                              void* d_out, int out_size)
{
    (void)in_sizes; (void)n_in; (void)out_size;
    const float* x    = (const float*)d_in[0];
    const float* mask = (const float*)d_in[1];
    const float* w1   = (const float*)d_in[2];
    const float* b1   = (const float*)d_in[3];
    const float* w2   = (const float*)d_in[4];
    const float* b2   = (const float*)d_in[5];
    const float* w3   = (const float*)d_in[6];
    const float* b3   = (const float*)d_in[7];
    const float* w4   = (const float*)d_in[8];
    const float* b4   = (const float*)d_in[9];
    const float* pw   = (const float*)d_in[10];
    float* out = (float*)d_out;

    prep_kernel<<<256, 256>>>(w2, w3, w4, pw);

    cudaFuncSetAttribute(mlp_kernel, cudaFuncAttributeMaxDynamicSharedMemorySize, SM_TOTAL);
    dim3 grid(NPOS / MT, BATCH);
    mlp_kernel<<<grid, NTHR, SM_TOTAL>>>(x, mask, w1, b1, b2, b3, b4);

    sortpool_kernel<<<BATCH * 2, 256>>>(mask, out);
}

// round 9
// speedup vs baseline: 3.0686x; 1.3070x over previous
#include <cuda_runtime.h>
#include <cuda_fp16.h>
#include <cstdint>

#define BATCH 1024
#define CIN   5
#define NPOS  512
#define DIM   256
#define C4    128
#define MT    128            // positions per CTA
#define AST   264            // act smem row stride (fp16): 132 words -> conflict-free
#define NTHR  512

// smem byte offsets
#define SM_XS    0                       // 5*128 f32 = 2560
#define SM_MK    2560                    // 128 f32 = 512
#define SM_BIAS  3072                    // 896 f32 = 3584
#define SM_ACT   6656                    // single fp16 act buffer (in-place across layers)
#define SM_WBUF  (SM_ACT + 67584)        // 74240: double-buffered weight chunks
#define WBUF_SZ  32768
#define SM_TOTAL (SM_WBUF + 2 * WBUF_SZ) // 139776 bytes

// per-chunk byte sizes (64 K-cols, fragment-packed fp16: 8B per (ks,c,t))
#define CHB_256  (4 * 256 * 4 * 8)       // 32768
#define CHB_128  (4 * 128 * 4 * 8)       // 16384

// ---------------- device scratch ----------------
__device__ float g_h[(size_t)BATCH * C4 * NPOS];       // 256 MB masked activations
__device__ float g_wtab[C4 * NPOS];
// fragment-packed fp16 weights per 64-K chunk:
//   record[((kc*4+ks)*C + c)*4 + t] = 8B { w(K0), w(K0+1), w(K0+8), w(K0+9) }, K0 = kc*64+ks*16+t*2
__device__ __align__(16) __half g_W2p[4 * 4 * 256 * 4 * 4];
__device__ __align__(16) __half g_W3p[4 * 4 * 256 * 4 * 4];
__device__ __align__(16) __half g_W4p[4 * 4 * 128 * 4 * 4];

// ---------------- helpers ----------------
__device__ __forceinline__ uint32_t smem_u32(const void* p) {
    uint32_t a;
    asm("{ .reg .u64 t; cvta.to.shared.u64 t, %1; cvt.u32.u64 %0, t; }" : "=r"(a) : "l"(p));
    return a;
}

__device__ __forceinline__ void mma16816h(float* d, const unsigned* a, const unsigned* b) {
    asm volatile(
        "mma.sync.aligned.m16n8k16.row.col.f32.f16.f16.f32 "
        "{%0,%1,%2,%3}, {%4,%5,%6,%7}, {%8,%9}, {%0,%1,%2,%3};"
        : "+f"(d[0]), "+f"(d[1]), "+f"(d[2]), "+f"(d[3])
        : "r"(a[0]), "r"(a[1]), "r"(a[2]), "r"(a[3]), "r"(b[0]), "r"(b[1]));
}

__device__ __forceinline__ unsigned pack_h2(float a, float b) {
    half2 p = __floats2half2_rn(a, b);
    return *(unsigned*)&p;
}

// all 512 threads: async-copy one weight chunk into ring buffer `buf`
__device__ __forceinline__ void prefetch_chunk(char* smem, int buf, const char* src,
                                               int bytes, int tid)
{
    uint32_t dst = smem_u32(smem + SM_WBUF + buf * WBUF_SZ);
    #pragma unroll 4
    for (int off = tid * 16; off < bytes; off += NTHR * 16)
        asm volatile("cp.async.cg.shared.global [%0], [%1], 16;"
                     :: "r"(dst + off), "l"(src + off));
    asm volatile("cp.async.commit_group;" ::: "memory");
}

// ---------------- prep: fragment-pack fp16 weights, pool table ----------------
__device__ __forceinline__ void pack4(__half* base, int rec, const float* w,
                                      int c, int ldw, int K0)
{
    __half v[4];
    #pragma unroll
    for (int u = 0; u < 4; u++)
        v[u] = __float2half_rn(w[c * ldw + K0 + (u >> 1) * 8 + (u & 1)]);
    *(uint2*)&base[rec * 4] = *(uint2*)v;
}

__global__ void prep_kernel(const float* __restrict__ w2, const float* __restrict__ w3,
                            const float* __restrict__ w4, const float* __restrict__ pw)
{
    int i = blockIdx.x * blockDim.x + threadIdx.x;   // 65536 threads

    if (i < 16384) {   // W2 / W3: t, c(256), ks(4), kc(4)
        int t = i & 3, c = (i >> 2) & 255, ks = (i >> 10) & 3, kc = (i >> 12) & 3;
        int K0 = kc * 64 + ks * 16 + t * 2;
        int rec = ((kc * 4 + ks) * 256 + c) * 4 + t;
        pack4(g_W2p, rec, w2, c, DIM, K0);
        pack4(g_W3p, rec, w3, c, DIM, K0);
    }
    if (i < 8192) {    // W4: t, c(128), ks(4), kc(4)
        int t = i & 3, c = (i >> 2) & 127, ks = (i >> 9) & 3, kc = (i >> 11) & 3;
        int K0 = kc * 64 + ks * 16 + t * 2;
        int rec = ((kc * 4 + ks) * 128 + c) * 4 + t;
        pack4(g_W4p, rec, w4, c, DIM, K0);
    }

    // pool weight table (128 x 512)
    int ch = i >> 9, n = i & 511;
    float ratio = (float)n / 511.0f;
    float pos = 20.0f * ratio;
    float fidx = floorf(pos);
    int idx = (int)fidx;
    float frac = pos - fidx;
    int idx2 = idx + 1; if (idx2 > 20) idx2 = 20;
    g_wtab[i] = (1.0f - frac) * pw[ch * 21 + idx] + frac * pw[ch * 21 + idx2];
}

// ---------------- mma layer over 4 double-buffered 64-K chunks, 2 m-tiles/warp ----------------
template<int COUT, int NT>
__device__ __forceinline__ void layer_mma(
    char* smem, const __half* __restrict__ wglob,
    const char* __restrict__ wnext, int next_bytes,
    const __half* aH,
    float (*acc0)[4], float (*acc1)[4],
    int tid, int wm, int wn, int g, int t2)
{
    const int CHB = 4 * COUT * 4 * 8;
    const int tq = t2 >> 1;           // lane & 3
    #pragma unroll 1
    for (int kc = 0; kc < 4; kc++) {
        asm volatile("cp.async.wait_group 0;" ::: "memory");
        __syncthreads();
        if (kc < 3)
            prefetch_chunk(smem, (kc + 1) & 1, (const char*)wglob + (size_t)(kc + 1) * CHB, CHB, tid);
        else if (wnext)
            prefetch_chunk(smem, 0, wnext, next_bytes, tid);

        const uint2* wf = (const uint2*)(smem + SM_WBUF + (kc & 1) * WBUF_SZ);

        #pragma unroll
        for (int ks = 0; ks < 4; ks++) {
            const int kcol = ks * 16 + t2;
            const int acol = kc * 64 + kcol;
            const int row0 = wm * 32 + g;         // m-tile 0
            const int row1 = row0 + 16;           // m-tile 1
            unsigned ah0[4], ah1[4];
            ah0[0] = *(const unsigned*)&aH[(row0    ) * AST + acol    ];
            ah0[1] = *(const unsigned*)&aH[(row0 + 8) * AST + acol    ];
            ah0[2] = *(const unsigned*)&aH[(row0    ) * AST + acol + 8];
            ah0[3] = *(const unsigned*)&aH[(row0 + 8) * AST + acol + 8];
            ah1[0] = *(const unsigned*)&aH[(row1    ) * AST + acol    ];
            ah1[1] = *(const unsigned*)&aH[(row1 + 8) * AST + acol    ];
            ah1[2] = *(const unsigned*)&aH[(row1    ) * AST + acol + 8];
            ah1[3] = *(const unsigned*)&aH[(row1 + 8) * AST + acol + 8];
            #pragma unroll
            for (int n8 = 0; n8 < NT; n8++) {
                const int c = wn * (NT * 8) + n8 * 8 + g;
                uint2 v = wf[(ks * COUT + c) * 4 + tq];   // LDS.64 B-fragment
                unsigned bh[2] = { v.x, v.y };
                mma16816h(acc0[n8], ah0, bh);
                mma16816h(acc1[n8], ah1, bh);
            }
        }
    }
}

// ---------------- fused 4-layer MLP (fp16 MMA), 128 positions per CTA, 512 threads ----------------
__global__ void __launch_bounds__(NTHR, 1)
mlp_kernel(const float* __restrict__ x, const float* __restrict__ mask,
           const float* __restrict__ w1,
           const float* __restrict__ b1, const float* __restrict__ b2,
           const float* __restrict__ b3, const float* __restrict__ b4)
{
    extern __shared__ char smem[];
    const int tid  = threadIdx.x;
    const int lane = tid & 31;
    const int warp = tid >> 5;       // 0..15
    const int wm   = warp & 3;       // 32-row group
    const int wn   = warp >> 2;      // 0..3 n-group
    const int g    = lane >> 2;
    const int t2   = (lane & 3) * 2;
    const int b    = blockIdx.y;
    const int n0   = blockIdx.x * MT;

    // kick off layer-2 chunk 0 immediately (covered by layer-1 scalar work)
    prefetch_chunk(smem, 0, (const char*)g_W2p, CHB_256, tid);

    float* xs    = (float*)(smem + SM_XS);
    float* mkS   = (float*)(smem + SM_MK);
    float* sBias = (float*)(smem + SM_BIAS);
    __half* aH   = (__half*)(smem + SM_ACT);

    // stage x tile, mask, biases
    for (int i = tid; i < CIN * MT; i += NTHR) {
        int k = i / MT, n = i % MT;
        xs[k * MT + n] = x[((size_t)b * CIN + k) * NPOS + n0 + n];
    }
    if (tid < MT) mkS[tid] = mask[(size_t)b * NPOS + n0 + tid] * (1.0f / NPOS);
    for (int i = tid; i < 896; i += NTHR) {
        float v;
        if      (i < 256) v = b1[i];
        else if (i < 512) v = b2[i - 256];
        else if (i < 768) v = b3[i - 512];
        else              v = b4[i - 768];
        sBias[i] = v;
    }
    __syncthreads();

    // ---- layer 1 (scalar f32, K=5): thread -> 2 channels x 32 positions
    {
        const int ch0 = (tid & 127) * 2;
        const int nh  = tid >> 7;            // 0..3
        float wr0[CIN], wr1[CIN];
        #pragma unroll
        for (int k = 0; k < CIN; k++) {
            wr0[k] = __ldg(&w1[ch0 * CIN + k]);
            wr1[k] = __ldg(&w1[(ch0 + 1) * CIN + k]);
        }
        const float bb0 = sBias[ch0], bb1 = sBias[ch0 + 1];
        #pragma unroll 4
        for (int nl = 0; nl < 32; nl++) {
            const int n = nh * 32 + nl;
            float a0 = bb0, a1 = bb1;
            #pragma unroll
            for (int k = 0; k < CIN; k++) {
                float xv = xs[k * MT + n];
                a0 += xv * wr0[k];
                a1 += xv * wr1[k];
            }
            a0 = fmaxf(a0, 0.0f); a1 = fmaxf(a1, 0.0f);
            *(unsigned*)&aH[n * AST + ch0] = pack_h2(a0, a1);
        }
    }
    __syncthreads();

    float acc0[8][4], acc1[8][4];

    // ---- layers 2 and 3 (in-place act update)
    #pragma unroll 1
    for (int L = 0; L < 2; L++) {
        #pragma unroll
        for (int i = 0; i < 8; i++) {
            acc0[i][0]=acc0[i][1]=acc0[i][2]=acc0[i][3]=0.0f;
            acc1[i][0]=acc1[i][1]=acc1[i][2]=acc1[i][3]=0.0f;
        }
        const __half* wg = (L == 0) ? g_W2p : g_W3p;
        const char* wnxt = (L == 0) ? (const char*)g_W3p : (const char*)g_W4p;
        const int nb = (L == 0) ? CHB_256 : CHB_128;
        layer_mma<256, 8>(smem, wg, wnxt, nb, aH, acc0, acc1, tid, wm, wn, g, t2);
        __syncthreads();                 // all MMA reads done before in-place overwrite
        const float* lb = sBias + 256 * (L + 1);
        #pragma unroll
        for (int n8 = 0; n8 < 8; n8++) {
            const int col = wn * 64 + n8 * 8 + t2;
            const float bb0 = lb[col], bb1 = lb[col + 1];
            #pragma unroll
            for (int half_ = 0; half_ < 2; half_++) {
                const int r0 = wm * 32 + g + half_ * 8;
                float v0 = fmaxf(acc0[n8][half_ * 2 + 0] + bb0, 0.0f);
                float v1 = fmaxf(acc0[n8][half_ * 2 + 1] + bb1, 0.0f);
                *(unsigned*)&aH[r0 * AST + col] = pack_h2(v0, v1);
                const int r1 = r0 + 16;
                v0 = fmaxf(acc1[n8][half_ * 2 + 0] + bb0, 0.0f);
                v1 = fmaxf(acc1[n8][half_ * 2 + 1] + bb1, 0.0f);
                *(unsigned*)&aH[r1 * AST + col] = pack_h2(v0, v1);
            }
        }
        __syncthreads();
    }

    // ---- layer 4: A -> transpose buffer (f32, overlays act area) -> g_h
    #pragma unroll
    for (int i = 0; i < 4; i++) {
        acc0[i][0]=acc0[i][1]=acc0[i][2]=acc0[i][3]=0.0f;
        acc1[i][0]=acc1[i][1]=acc1[i][2]=acc1[i][3]=0.0f;
    }
    layer_mma<128, 4>(smem, g_W4p, (const char*)0, 0, aH, acc0, acc1, tid, wm, wn, g, t2);

    float* sT = (float*)(smem + SM_ACT);    // [128 c][132 n] f32 = 67584 B, overlays act buffer
    __syncthreads();                        // all MMA reads of acts done
    #pragma unroll
    for (int n8 = 0; n8 < 4; n8++) {
        const int c = wn * 32 + n8 * 8 + t2;
        const float bb0 = sBias[768 + c], bb1 = sBias[768 + c + 1];
        #pragma unroll
        for (int half_ = 0; half_ < 2; half_++) {
            const int n0r = wm * 32 + g + half_ * 8;
            sT[(c    ) * 132 + n0r] = acc0[n8][half_ * 2 + 0] + bb0;
            sT[(c + 1) * 132 + n0r] = acc0[n8][half_ * 2 + 1] + bb1;
            sT[(c    ) * 132 + n0r + 16] = acc1[n8][half_ * 2 + 0] + bb0;
            sT[(c + 1) * 132 + n0r + 16] = acc1[n8][half_ * 2 + 1] + bb1;
        }
    }
    __syncthreads();
    {
        const int c   = tid >> 2;           // 0..127
        const int seg = tid & 3;            // 32-position segment
        float* dst = g_h + (((size_t)b * C4 + c) << 9) + n0 + seg * 32;
        #pragma unroll
        for (int i = 0; i < 8; i++) {
            const int nn = seg * 32 + i * 4;
            float4 v = *(float4*)&sT[c * 132 + nn];
            v.x *= mkS[nn + 0]; v.y *= mkS[nn + 1];
            v.z *= mkS[nn + 2]; v.w *= mkS[nn + 3];
            *(float4*)&dst[i * 4] = v;
        }
    }
}

// ---------------- warp-register bitonic sort (desc, 512) + weighted pool ----------------
__global__ void __launch_bounds__(256)
sortpool_kernel(const float* __restrict__ mask, float* __restrict__ out)
{
    const int b    = blockIdx.x >> 1;
    const int hf   = blockIdx.x & 1;
    const int tid  = threadIdx.x;
    const int lane = tid & 31;
    const int warp = tid >> 5;
    __shared__ float sred[8];

    // size feature: mean(mask) * 4 (half 0 only)
    if (hf == 0) {
        float s = mask[(size_t)b * NPOS + tid] + mask[(size_t)b * NPOS + tid + 256];
        #pragma unroll
        for (int o = 16; o > 0; o >>= 1) s += __shfl_xor_sync(0xffffffffu, s, o);
        if (lane == 0) sred[warp] = s;
        __syncthreads();
        if (tid == 0) {
            float t = 0.0f;
            #pragma unroll
            for (int i = 0; i < 8; i++) t += sred[i];
            out[b * 129 + 128] = t * (4.0f / NPOS);
        }
    }

    for (int c = hf * 64 + warp; c < hf * 64 + 64; c += 8) {
        const float* row = g_h + (((size_t)b * C4 + c) << 9);
        float v[16];
        #pragma unroll
        for (int r = 0; r < 16; r++) v[r] = row[r * 32 + lane];

        #pragma unroll 1
        for (int k = 2; k <= 512; k <<= 1) {
            #pragma unroll 1
            for (int j = k >> 1; j > 0; j >>= 1) {
                if (j >= 32) {
                    int rj = j >> 5, km = k >> 5;
                    #pragma unroll
                    for (int r = 0; r < 16; r++) {
                        if ((r & rj) == 0) {
                            int r2 = r | rj;
                            bool asc = (r & km) != 0;
                            float a = v[r], bb = v[r2];
                            float lo = fminf(a, bb), hi = fmaxf(a, bb);
                            v[r]  = asc ? lo : hi;
                            v[r2] = asc ? hi : lo;
                        }
                    }
                } else {
                    #pragma unroll
                    for (int r = 0; r < 16; r++) {
                        int i = (r << 5) | lane;
                        bool asc   = (i & k) != 0;
                        bool lower = (lane & j) == 0;
                        float other = __shfl_xor_sync(0xffffffffu, v[r], j);
                        bool takeMin = (lower == asc);
                        v[r] = takeMin ? fminf(v[r], other) : fmaxf(v[r], other);
                    }
                }
            }
        }

        const float* wrow = g_wtab + c * NPOS;
        float s = 0.0f;
        #pragma unroll
        for (int r = 0; r < 16; r++) s += v[r] * wrow[r * 32 + lane];
        #pragma unroll
        for (int o = 16; o > 0; o >>= 1) s += __shfl_xor_sync(0xffffffffu, s, o);
        if (lane == 0) out[b * 129 + c] = s;
    }
}

// ---------------- launch ----------------
extern "C" void kernel_launch(void* const* d_in, const int* in_sizes, int n_in,
                              void* d_out, int out_size)
{
    (void)in_sizes; (void)n_in; (void)out_size;
    const float* x    = (const float*)d_in[0];
    const float* mask = (const float*)d_in[1];
    const float* w1   = (const float*)d_in[2];
    const float* b1   = (const float*)d_in[3];
    const float* w2   = (const float*)d_in[4];
    const float* b2   = (const float*)d_in[5];
    const float* w3   = (const float*)d_in[6];
    const float* b3   = (const float*)d_in[7];
    const float* w4   = (const float*)d_in[8];
    const float* b4   = (const float*)d_in[9];
    const float* pw   = (const float*)d_in[10];
    float* out = (float*)d_out;

    prep_kernel<<<256, 256>>>(w2, w3, w4, pw);

    cudaFuncSetAttribute(mlp_kernel, cudaFuncAttributeMaxDynamicSharedMemorySize, SM_TOTAL);
    dim3 grid(NPOS / MT, BATCH);
    mlp_kernel<<<grid, NTHR, SM_TOTAL>>>(x, mask, w1, b1, b2, b3, b4);

    sortpool_kernel<<<BATCH * 2, 256>>>(mask, out);
}

// round 10
// speedup vs baseline: 3.0772x; 1.0028x over previous
#include <cuda_runtime.h>
#include <cuda_fp16.h>
#include <cstdint>

#define BATCH 1024
#define CIN   5
#define NPOS  512
#define DIM   256
#define C4    128
#define MT    128            // positions per CTA
#define AST   264            // act smem row stride (fp16): 132 words -> conflict-free
#define NTHR  512

// smem byte offsets
#define SM_XS    0                       // 5*128 f32 = 2560
#define SM_MK    2560                    // 128 f32 = 512
#define SM_BIAS  3072                    // 896 f32 = 3584
#define SM_ACT   6656                    // single fp16 act buffer (in-place across layers)
#define SM_WBUF  (SM_ACT + 67584)        // 74240: double-buffered weight chunks
#define WBUF_SZ  32768
#define SM_TOTAL (SM_WBUF + 2 * WBUF_SZ) // 139776 bytes

// per-chunk byte sizes (64 K-cols, fragment-packed fp16: 8B per (ks,c,t))
#define CHB_256  (4 * 256 * 4 * 8)       // 32768
#define CHB_128  (4 * 128 * 4 * 8)       // 16384

// ---------------- device scratch ----------------
__device__ float g_h[(size_t)BATCH * C4 * NPOS];       // 256 MB masked activations
__device__ float g_wtab[C4 * NPOS];
// fragment-packed fp16 weights per 64-K chunk:
//   record[((kc*4+ks)*C + c)*4 + t] = 8B { w(K0), w(K0+1), w(K0+8), w(K0+9) }, K0 = kc*64+ks*16+t*2
__device__ __align__(16) __half g_W2p[4 * 4 * 256 * 4 * 4];
__device__ __align__(16) __half g_W3p[4 * 4 * 256 * 4 * 4];
__device__ __align__(16) __half g_W4p[4 * 4 * 128 * 4 * 4];

// ---------------- helpers ----------------
__device__ __forceinline__ uint32_t smem_u32(const void* p) {
    uint32_t a;
    asm("{ .reg .u64 t; cvta.to.shared.u64 t, %1; cvt.u32.u64 %0, t; }" : "=r"(a) : "l"(p));
    return a;
}

__device__ __forceinline__ void mma16816h(float* d, const unsigned* a, const unsigned* b) {
    asm volatile(
        "mma.sync.aligned.m16n8k16.row.col.f32.f16.f16.f32 "
        "{%0,%1,%2,%3}, {%4,%5,%6,%7}, {%8,%9}, {%0,%1,%2,%3};"
        : "+f"(d[0]), "+f"(d[1]), "+f"(d[2]), "+f"(d[3])
        : "r"(a[0]), "r"(a[1]), "r"(a[2]), "r"(a[3]), "r"(b[0]), "r"(b[1]));
}

__device__ __forceinline__ unsigned pack_h2(float a, float b) {
    half2 p = __floats2half2_rn(a, b);
    return *(unsigned*)&p;
}

// all 512 threads: async-copy one weight chunk into ring buffer `buf`
__device__ __forceinline__ void prefetch_chunk(char* smem, int buf, const char* src,
                                               int bytes, int tid)
{
    uint32_t dst = smem_u32(smem + SM_WBUF + buf * WBUF_SZ);
    #pragma unroll 4
    for (int off = tid * 16; off < bytes; off += NTHR * 16)
        asm volatile("cp.async.cg.shared.global [%0], [%1], 16;"
                     :: "r"(dst + off), "l"(src + off));
    asm volatile("cp.async.commit_group;" ::: "memory");
}

// ---------------- prep: fragment-pack fp16 weights, pool table ----------------
__device__ __forceinline__ void pack4(__half* base, int rec, const float* w,
                                      int c, int ldw, int K0)
{
    __half v[4];
    #pragma unroll
    for (int u = 0; u < 4; u++)
        v[u] = __float2half_rn(w[c * ldw + K0 + (u >> 1) * 8 + (u & 1)]);
    *(uint2*)&base[rec * 4] = *(uint2*)v;
}

__global__ void prep_kernel(const float* __restrict__ w2, const float* __restrict__ w3,
                            const float* __restrict__ w4, const float* __restrict__ pw)
{
    int i = blockIdx.x * blockDim.x + threadIdx.x;   // 65536 threads

    if (i < 16384) {   // W2 / W3: t, c(256), ks(4), kc(4)
        int t = i & 3, c = (i >> 2) & 255, ks = (i >> 10) & 3, kc = (i >> 12) & 3;
        int K0 = kc * 64 + ks * 16 + t * 2;
        int rec = ((kc * 4 + ks) * 256 + c) * 4 + t;
        pack4(g_W2p, rec, w2, c, DIM, K0);
        pack4(g_W3p, rec, w3, c, DIM, K0);
    }
    if (i < 8192) {    // W4: t, c(128), ks(4), kc(4)
        int t = i & 3, c = (i >> 2) & 127, ks = (i >> 9) & 3, kc = (i >> 11) & 3;
        int K0 = kc * 64 + ks * 16 + t * 2;
        int rec = ((kc * 4 + ks) * 128 + c) * 4 + t;
        pack4(g_W4p, rec, w4, c, DIM, K0);
    }

    // pool weight table (128 x 512)
    int ch = i >> 9, n = i & 511;
    float ratio = (float)n / 511.0f;
    float pos = 20.0f * ratio;
    float fidx = floorf(pos);
    int idx = (int)fidx;
    float frac = pos - fidx;
    int idx2 = idx + 1; if (idx2 > 20) idx2 = 20;
    g_wtab[i] = (1.0f - frac) * pw[ch * 21 + idx] + frac * pw[ch * 21 + idx2];
}

// ---------------- mma layer over 4 double-buffered 64-K chunks, 2 m-tiles/warp ----------------
template<int COUT, int NT>
__device__ __forceinline__ void layer_mma(
    char* smem, const __half* __restrict__ wglob,
    const char* __restrict__ wnext, int next_bytes,
    const __half* aH,
    float (*acc0)[4], float (*acc1)[4],
    int tid, int wm, int wn, int g, int t2)
{
    const int CHB = 4 * COUT * 4 * 8;
    const int tq = t2 >> 1;           // lane & 3
    #pragma unroll 1
    for (int kc = 0; kc < 4; kc++) {
        asm volatile("cp.async.wait_group 0;" ::: "memory");
        __syncthreads();
        if (kc < 3)
            prefetch_chunk(smem, (kc + 1) & 1, (const char*)wglob + (size_t)(kc + 1) * CHB, CHB, tid);
        else if (wnext)
            prefetch_chunk(smem, 0, wnext, next_bytes, tid);

        const uint2* wf = (const uint2*)(smem + SM_WBUF + (kc & 1) * WBUF_SZ);

        #pragma unroll
        for (int ks = 0; ks < 4; ks++) {
            const int kcol = ks * 16 + t2;
            const int acol = kc * 64 + kcol;
            const int row0 = wm * 32 + g;         // m-tile 0
            const int row1 = row0 + 16;           // m-tile 1
            unsigned ah0[4], ah1[4];
            ah0[0] = *(const unsigned*)&aH[(row0    ) * AST + acol    ];
            ah0[1] = *(const unsigned*)&aH[(row0 + 8) * AST + acol    ];
            ah0[2] = *(const unsigned*)&aH[(row0    ) * AST + acol + 8];
            ah0[3] = *(const unsigned*)&aH[(row0 + 8) * AST + acol + 8];
            ah1[0] = *(const unsigned*)&aH[(row1    ) * AST + acol    ];
            ah1[1] = *(const unsigned*)&aH[(row1 + 8) * AST + acol    ];
            ah1[2] = *(const unsigned*)&aH[(row1    ) * AST + acol + 8];
            ah1[3] = *(const unsigned*)&aH[(row1 + 8) * AST + acol + 8];
            #pragma unroll
            for (int n8 = 0; n8 < NT; n8++) {
                const int c = wn * (NT * 8) + n8 * 8 + g;
                uint2 v = wf[(ks * COUT + c) * 4 + tq];   // LDS.64 B-fragment
                unsigned bh[2] = { v.x, v.y };
                mma16816h(acc0[n8], ah0, bh);
                mma16816h(acc1[n8], ah1, bh);
            }
        }
    }
}

// ---------------- fused 4-layer MLP (fp16 MMA), 128 positions per CTA, 512 threads ----------------
__global__ void __launch_bounds__(NTHR, 1)
mlp_kernel(const float* __restrict__ x, const float* __restrict__ mask,
           const float* __restrict__ w1,
           const float* __restrict__ b1, const float* __restrict__ b2,
           const float* __restrict__ b3, const float* __restrict__ b4)
{
    extern __shared__ char smem[];
    const int tid  = threadIdx.x;
    const int lane = tid & 31;
    const int warp = tid >> 5;       // 0..15
    const int wm   = warp & 3;       // 32-row group
    const int wn   = warp >> 2;      // 0..3 n-group
    const int g    = lane >> 2;
    const int t2   = (lane & 3) * 2;
    const int b    = blockIdx.y;
    const int n0   = blockIdx.x * MT;

    // kick off layer-2 chunk 0 immediately (covered by layer-1 scalar work)
    prefetch_chunk(smem, 0, (const char*)g_W2p, CHB_256, tid);

    float* xs    = (float*)(smem + SM_XS);
    float* mkS   = (float*)(smem + SM_MK);
    float* sBias = (float*)(smem + SM_BIAS);
    __half* aH   = (__half*)(smem + SM_ACT);

    // stage x tile, mask, biases
    for (int i = tid; i < CIN * MT; i += NTHR) {
        int k = i / MT, n = i % MT;
        xs[k * MT + n] = x[((size_t)b * CIN + k) * NPOS + n0 + n];
    }
    if (tid < MT) mkS[tid] = mask[(size_t)b * NPOS + n0 + tid] * (1.0f / NPOS);
    for (int i = tid; i < 896; i += NTHR) {
        float v;
        if      (i < 256) v = b1[i];
        else if (i < 512) v = b2[i - 256];
        else if (i < 768) v = b3[i - 512];
        else              v = b4[i - 768];
        sBias[i] = v;
    }
    __syncthreads();

    // ---- layer 1 (scalar f32, K=5): thread -> 2 channels x 32 positions
    {
        const int ch0 = (tid & 127) * 2;
        const int nh  = tid >> 7;            // 0..3
        float wr0[CIN], wr1[CIN];
        #pragma unroll
        for (int k = 0; k < CIN; k++) {
            wr0[k] = __ldg(&w1[ch0 * CIN + k]);
            wr1[k] = __ldg(&w1[(ch0 + 1) * CIN + k]);
        }
        const float bb0 = sBias[ch0], bb1 = sBias[ch0 + 1];
        #pragma unroll 4
        for (int nl = 0; nl < 32; nl++) {
            const int n = nh * 32 + nl;
            float a0 = bb0, a1 = bb1;
            #pragma unroll
            for (int k = 0; k < CIN; k++) {
                float xv = xs[k * MT + n];
                a0 += xv * wr0[k];
                a1 += xv * wr1[k];
            }
            a0 = fmaxf(a0, 0.0f); a1 = fmaxf(a1, 0.0f);
            *(unsigned*)&aH[n * AST + ch0] = pack_h2(a0, a1);
        }
    }
    __syncthreads();

    float acc0[8][4], acc1[8][4];

    // ---- layers 2 and 3 (in-place act update)
    #pragma unroll 1
    for (int L = 0; L < 2; L++) {
        #pragma unroll
        for (int i = 0; i < 8; i++) {
            acc0[i][0]=acc0[i][1]=acc0[i][2]=acc0[i][3]=0.0f;
            acc1[i][0]=acc1[i][1]=acc1[i][2]=acc1[i][3]=0.0f;
        }
        const __half* wg = (L == 0) ? g_W2p : g_W3p;
        const char* wnxt = (L == 0) ? (const char*)g_W3p : (const char*)g_W4p;
        const int nb = (L == 0) ? CHB_256 : CHB_128;
        layer_mma<256, 8>(smem, wg, wnxt, nb, aH, acc0, acc1, tid, wm, wn, g, t2);
        __syncthreads();                 // all MMA reads done before in-place overwrite
        const float* lb = sBias + 256 * (L + 1);
        #pragma unroll
        for (int n8 = 0; n8 < 8; n8++) {
            const int col = wn * 64 + n8 * 8 + t2;
            const float bb0 = lb[col], bb1 = lb[col + 1];
            #pragma unroll
            for (int half_ = 0; half_ < 2; half_++) {
                const int r0 = wm * 32 + g + half_ * 8;
                float v0 = fmaxf(acc0[n8][half_ * 2 + 0] + bb0, 0.0f);
                float v1 = fmaxf(acc0[n8][half_ * 2 + 1] + bb1, 0.0f);
                *(unsigned*)&aH[r0 * AST + col] = pack_h2(v0, v1);
                const int r1 = r0 + 16;
                v0 = fmaxf(acc1[n8][half_ * 2 + 0] + bb0, 0.0f);
                v1 = fmaxf(acc1[n8][half_ * 2 + 1] + bb1, 0.0f);
                *(unsigned*)&aH[r1 * AST + col] = pack_h2(v0, v1);
            }
        }
        __syncthreads();
    }

    // ---- layer 4: A -> transpose buffer (f32, overlays act area) -> g_h
    #pragma unroll
    for (int i = 0; i < 4; i++) {
        acc0[i][0]=acc0[i][1]=acc0[i][2]=acc0[i][3]=0.0f;
        acc1[i][0]=acc1[i][1]=acc1[i][2]=acc1[i][3]=0.0f;
    }
    layer_mma<128, 4>(smem, g_W4p, (const char*)0, 0, aH, acc0, acc1, tid, wm, wn, g, t2);

    float* sT = (float*)(smem + SM_ACT);    // [128 c][132 n] f32 = 67584 B, overlays act buffer
    __syncthreads();                        // all MMA reads of acts done
    #pragma unroll
    for (int n8 = 0; n8 < 4; n8++) {
        const int c = wn * 32 + n8 * 8 + t2;
        const float bb0 = sBias[768 + c], bb1 = sBias[768 + c + 1];
        #pragma unroll
        for (int half_ = 0; half_ < 2; half_++) {
            const int n0r = wm * 32 + g + half_ * 8;
            sT[(c    ) * 132 + n0r] = acc0[n8][half_ * 2 + 0] + bb0;
            sT[(c + 1) * 132 + n0r] = acc0[n8][half_ * 2 + 1] + bb1;
            sT[(c    ) * 132 + n0r + 16] = acc1[n8][half_ * 2 + 0] + bb0;
            sT[(c + 1) * 132 + n0r + 16] = acc1[n8][half_ * 2 + 1] + bb1;
        }
    }
    __syncthreads();
    {
        const int c   = tid >> 2;           // 0..127
        const int seg = tid & 3;            // 32-position segment
        float* dst = g_h + (((size_t)b * C4 + c) << 9) + n0 + seg * 32;
        #pragma unroll
        for (int i = 0; i < 8; i++) {
            const int nn = seg * 32 + i * 4;
            float4 v = *(float4*)&sT[c * 132 + nn];
            v.x *= mkS[nn + 0]; v.y *= mkS[nn + 1];
            v.z *= mkS[nn + 2]; v.w *= mkS[nn + 3];
            *(float4*)&dst[i * 4] = v;
        }
    }
}

// ---------------- warp-register bitonic sort (desc, 512) + weighted pool ----------------
__global__ void __launch_bounds__(256)
sortpool_kernel(const float* __restrict__ mask, float* __restrict__ out)
{
    const int b    = blockIdx.x >> 1;
    const int hf   = blockIdx.x & 1;
    const int tid  = threadIdx.x;
    const int lane = tid & 31;
    const int warp = tid >> 5;
    __shared__ float sred[8];

    // size feature: mean(mask) * 4 (half 0 only)
    if (hf == 0) {
        float s = mask[(size_t)b * NPOS + tid] + mask[(size_t)b * NPOS + tid + 256];
        #pragma unroll
        for (int o = 16; o > 0; o >>= 1) s += __shfl_xor_sync(0xffffffffu, s, o);
        if (lane == 0) sred[warp] = s;
        __syncthreads();
        if (tid == 0) {
            float t = 0.0f;
            #pragma unroll
            for (int i = 0; i < 8; i++) t += sred[i];
            out[b * 129 + 128] = t * (4.0f / NPOS);
        }
    }

    for (int c = hf * 64 + warp; c < hf * 64 + 64; c += 8) {
        const float* row = g_h + (((size_t)b * C4 + c) << 9);
        float v[16];
        #pragma unroll
        for (int r = 0; r < 16; r++) v[r] = row[r * 32 + lane];

        #pragma unroll 1
        for (int k = 2; k <= 512; k <<= 1) {
            #pragma unroll 1
            for (int j = k >> 1; j > 0; j >>= 1) {
                if (j >= 32) {
                    int rj = j >> 5, km = k >> 5;
                    #pragma unroll
                    for (int r = 0; r < 16; r++) {
                        if ((r & rj) == 0) {
                            int r2 = r | rj;
                            bool asc = (r & km) != 0;
                            float a = v[r], bb = v[r2];
                            float lo = fminf(a, bb), hi = fmaxf(a, bb);
                            v[r]  = asc ? lo : hi;
                            v[r2] = asc ? hi : lo;
                        }
                    }
                } else {
                    #pragma unroll
                    for (int r = 0; r < 16; r++) {
                        int i = (r << 5) | lane;
                        bool asc   = (i & k) != 0;
                        bool lower = (lane & j) == 0;
                        float other = __shfl_xor_sync(0xffffffffu, v[r], j);
                        bool takeMin = (lower == asc);
                        v[r] = takeMin ? fminf(v[r], other) : fmaxf(v[r], other);
                    }
                }
            }
        }

        const float* wrow = g_wtab + c * NPOS;
        float s = 0.0f;
        #pragma unroll
        for (int r = 0; r < 16; r++) s += v[r] * wrow[r * 32 + lane];
        #pragma unroll
        for (int o = 16; o > 0; o >>= 1) s += __shfl_xor_sync(0xffffffffu, s, o);
        if (lane == 0) out[b * 129 + c] = s;
    }
}

// ---------------- launch ----------------
extern "C" void kernel_launch(void* const* d_in, const int* in_sizes, int n_in,
                              void* d_out, int out_size)
{
    (void)in_sizes; (void)n_in; (void)out_size;
    const float* x    = (const float*)d_in[0];
    const float* mask = (const float*)d_in[1];
    const float* w1   = (const float*)d_in[2];
    const float* b1   = (const float*)d_in[3];
    const float* w2   = (const float*)d_in[4];
    const float* b2   = (const float*)d_in[5];
    const float* w3   = (const float*)d_in[6];
    const float* b3   = (const float*)d_in[7];
    const float* w4   = (const float*)d_in[8];
    const float* b4   = (const float*)d_in[9];
    const float* pw   = (const float*)d_in[10];
    float* out = (float*)d_out;

    prep_kernel<<<256, 256>>>(w2, w3, w4, pw);

    cudaFuncSetAttribute(mlp_kernel, cudaFuncAttributeMaxDynamicSharedMemorySize, SM_TOTAL);
    dim3 grid(NPOS / MT, BATCH);
    mlp_kernel<<<grid, NTHR, SM_TOTAL>>>(x, mask, w1, b1, b2, b3, b4);

    sortpool_kernel<<<BATCH * 2, 256>>>(mask, out);
}